// round 4
// baseline (speedup 1.0000x reference)
#include <cuda_runtime.h>
#include <cuda_bf16.h>
#include <math.h>

#define N_NODES 50000
#define N_EDGES 800000
#define HIDDEN  256
#define HEADS   4
#define HEAD_DIM 64
#define LAYERS  3
#define NUM_GRAPHS 64
#define NEG_SLOPE 0.2f

// ---------------- scratch (device globals; no allocation allowed) ----------------
__device__ float g_h   [(long long)N_NODES * HIDDEN];
__device__ float g_hp  [(long long)N_NODES * HIDDEN];
__device__ float g_agg [(long long)N_NODES * HIDDEN];
__device__ float g_ss  [N_NODES * HEADS];
__device__ float g_sd  [N_NODES * HEADS];
__device__ float g_m   [N_NODES * HEADS];
__device__ float g_den [N_NODES * HEADS];
__device__ float g_logit[(long long)N_EDGES * HEADS];
__device__ float g_c   [HEADS * 3];
__device__ float g_pool[NUM_GRAPHS * HIDDEN];
__device__ float g_cnt [NUM_GRAPHS];

// ---------------- helpers ----------------
__device__ __forceinline__ float elu1(float v) {
    return v > 0.f ? v : expm1f(v);
}

__device__ __forceinline__ void atomicMaxFloat(float* addr, float value) {
    if (value >= 0.f) {
        atomicMax((int*)addr, __float_as_int(value));
    } else {
        atomicMin((unsigned int*)addr, __float_as_uint(value));
    }
}

__device__ __forceinline__ float warp_sum(float v) {
    #pragma unroll
    for (int o = 16; o > 0; o >>= 1) v += __shfl_xor_sync(0xFFFFFFFFu, v, o);
    return v;
}

// ---------------- init pooling buffers ----------------
__global__ void init_pool_kernel() {
    int i = blockIdx.x * blockDim.x + threadIdx.x;
    if (i < NUM_GRAPHS * HIDDEN) g_pool[i] = 0.f;
    if (i < NUM_GRAPHS) g_cnt[i] = 0.f;
}

// ---------------- input projection + LN + ELU ----------------
__global__ void input_proj_kernel(const float* __restrict__ x,
                                  const float* __restrict__ Win,
                                  const float* __restrict__ bin,
                                  const float* __restrict__ lg,
                                  const float* __restrict__ lb) {
    int n = blockIdx.x;
    int j = threadIdx.x;
    __shared__ float xs[8];
    __shared__ float red[HIDDEN];
    if (j < 8) xs[j] = x[n * 8 + j];
    __syncthreads();
    float y = bin[j];
    #pragma unroll
    for (int k = 0; k < 8; k++) y += xs[k] * Win[k * HIDDEN + j];
    // mean
    red[j] = y; __syncthreads();
    for (int s = HIDDEN / 2; s > 0; s >>= 1) { if (j < s) red[j] += red[j + s]; __syncthreads(); }
    float mu = red[0] * (1.f / HIDDEN);
    __syncthreads();
    float d = y - mu;
    red[j] = d * d; __syncthreads();
    for (int s = HIDDEN / 2; s > 0; s >>= 1) { if (j < s) red[j] += red[j + s]; __syncthreads(); }
    float var = red[0] * (1.f / HIDDEN);
    float v = d * rsqrtf(var + 1e-5f) * lg[j] + lb[j];
    g_h[(long long)n * HIDDEN + j] = elu1(v);
}

// ---------------- SGEMM: C[M,256] = A[M,256] @ B[256,256] + bias ----------------
__global__ void sgemm_bias_kernel(const float* __restrict__ A,
                                  const float* __restrict__ B,
                                  const float* __restrict__ bias,
                                  float* __restrict__ C,
                                  int M) {
    const int Nn = 256, K = 256;
    const int BM = 128, BN = 128, BK = 8, TM = 8, TN = 8;
    __shared__ float As[BK][BM];
    __shared__ float Bs[BK][BN];
    int tid = threadIdx.x;
    int cRow = blockIdx.y, cCol = blockIdx.x;
    int tRow = tid / (BN / TN);     // 0..15
    int tCol = tid % (BN / TN);     // 0..15
    float acc[TM][TN];
    #pragma unroll
    for (int i = 0; i < TM; i++)
        #pragma unroll
        for (int j = 0; j < TN; j++) acc[i][j] = 0.f;
    float regM[TM], regN[TN];

    int aRow = tid >> 1;            // 0..127
    int aCol = (tid & 1) * 4;       // 0 or 4
    int bRow = tid >> 5;            // 0..7
    int bCol = (tid & 31) * 4;      // 0..124

    const float* Ab = A + (long long)cRow * BM * K;
    const float* Bb = B + cCol * BN;
    int mRow = cRow * BM + aRow;

    for (int kt = 0; kt < K; kt += BK) {
        float4 av = (mRow < M) ? *(const float4*)&Ab[aRow * K + kt + aCol]
                               : make_float4(0.f, 0.f, 0.f, 0.f);
        As[aCol + 0][aRow] = av.x;
        As[aCol + 1][aRow] = av.y;
        As[aCol + 2][aRow] = av.z;
        As[aCol + 3][aRow] = av.w;
        float4 bv = *(const float4*)&Bb[(long long)(kt + bRow) * Nn + bCol];
        *(float4*)&Bs[bRow][bCol] = bv;
        __syncthreads();
        #pragma unroll
        for (int k = 0; k < BK; k++) {
            #pragma unroll
            for (int i = 0; i < TM; i++) regM[i] = As[k][tRow * TM + i];
            #pragma unroll
            for (int j = 0; j < TN; j++) regN[j] = Bs[k][tCol * TN + j];
            #pragma unroll
            for (int i = 0; i < TM; i++)
                #pragma unroll
                for (int j = 0; j < TN; j++) acc[i][j] += regM[i] * regN[j];
        }
        __syncthreads();
    }
    #pragma unroll
    for (int i = 0; i < TM; i++) {
        int row = cRow * BM + tRow * TM + i;
        if (row < M) {
            #pragma unroll
            for (int j = 0; j < TN; j += 4) {
                int col = cCol * BN + tCol * TN + j;
                float4 v;
                v.x = acc[i][j + 0] + bias[col + 0];
                v.y = acc[i][j + 1] + bias[col + 1];
                v.z = acc[i][j + 2] + bias[col + 2];
                v.w = acc[i][j + 3] + bias[col + 3];
                *(float4*)&C[(long long)row * Nn + col] = v;
            }
        }
    }
}

// ---------------- per-layer: c[h][k] = sum_d We[k, h*64+d] * a_e[h,d] ----------------
__global__ void compute_c_kernel(const float* __restrict__ We,
                                 const float* __restrict__ ae) {
    int i = threadIdx.x;
    if (i >= HEADS * 3) return;
    int hh = i / 3, k = i % 3;
    float s = 0.f;
    for (int d = 0; d < HEAD_DIM; d++)
        s += We[k * HIDDEN + hh * HEAD_DIM + d] * ae[hh * HEAD_DIM + d];
    g_c[i] = s;
}

// ---------------- node attention scores + init m/den + zero agg ----------------
__global__ void node_score_kernel(const float* __restrict__ as_,
                                  const float* __restrict__ ad_) {
    int gw = (blockIdx.x * blockDim.x + threadIdx.x) >> 5;
    int lane = threadIdx.x & 31;
    if (gw >= N_NODES * HEADS) return;
    int n = gw >> 2, hh = gw & 3;
    const float* row = g_hp + (long long)n * HIDDEN + hh * HEAD_DIM;
    float v0 = row[lane], v1 = row[lane + 32];
    float s = v0 * as_[hh * HEAD_DIM + lane] + v1 * as_[hh * HEAD_DIM + lane + 32];
    float t = v0 * ad_[hh * HEAD_DIM + lane] + v1 * ad_[hh * HEAD_DIM + lane + 32];
    s = warp_sum(s);
    t = warp_sum(t);
    float* ag = g_agg + (long long)n * HIDDEN + hh * HEAD_DIM;
    ag[lane] = 0.f;
    ag[lane + 32] = 0.f;
    if (lane == 0) {
        g_ss[gw] = s;
        g_sd[gw] = t;
        g_m[gw] = -INFINITY;
        g_den[gw] = 0.f;
    }
}

// ---------------- edge pass 1: logits + segment max ----------------
__global__ void edge_logit_kernel(const int* __restrict__ ei,
                                  const float* __restrict__ ea) {
    int e = blockIdx.x * blockDim.x + threadIdx.x;
    if (e >= N_EDGES) return;
    int s = ei[e];
    int d = ei[N_EDGES + e];
    float a0 = ea[e * 3 + 0], a1 = ea[e * 3 + 1], a2 = ea[e * 3 + 2];
    #pragma unroll
    for (int hh = 0; hh < HEADS; hh++) {
        float l = g_ss[s * 4 + hh] + g_sd[d * 4 + hh]
                + a0 * g_c[hh * 3 + 0] + a1 * g_c[hh * 3 + 1] + a2 * g_c[hh * 3 + 2];
        l = l > 0.f ? l : NEG_SLOPE * l;
        g_logit[(long long)e * 4 + hh] = l;
        atomicMaxFloat(&g_m[d * 4 + hh], l);
    }
}

// ---------------- edge pass 2: exp + segment sum ----------------
__global__ void edge_exp_kernel(const int* __restrict__ ei) {
    int e = blockIdx.x * blockDim.x + threadIdx.x;
    if (e >= N_EDGES) return;
    int d = ei[N_EDGES + e];
    #pragma unroll
    for (int hh = 0; hh < HEADS; hh++) {
        float v = expf(g_logit[(long long)e * 4 + hh] - g_m[d * 4 + hh]);
        g_logit[(long long)e * 4 + hh] = v;
        atomicAdd(&g_den[d * 4 + hh], v);
    }
}

// ---------------- edge pass 3: weighted message scatter ----------------
__global__ void edge_msg_kernel(const int* __restrict__ ei) {
    int gw = (blockIdx.x * blockDim.x + threadIdx.x) >> 5;
    int lane = threadIdx.x & 31;
    if (gw >= N_EDGES) return;
    int s = ei[gw];
    int d = ei[N_EDGES + gw];
    #pragma unroll
    for (int it = 0; it < 2; it++) {
        int j = it * 128 + lane * 4;
        int hh = j >> 6;
        float alpha = g_logit[(long long)gw * 4 + hh] / fmaxf(g_den[d * 4 + hh], 1e-16f);
        float4 v = *(const float4*)&g_hp[(long long)s * HIDDEN + j];
        float* base = &g_agg[(long long)d * HIDDEN + j];
        atomicAdd(base + 0, v.x * alpha);
        atomicAdd(base + 1, v.y * alpha);
        atomicAdd(base + 2, v.z * alpha);
        atomicAdd(base + 3, v.w * alpha);
    }
}

// ---------------- residual + ELU ----------------
__global__ void combine_kernel() {
    long long i = (long long)blockIdx.x * blockDim.x + threadIdx.x;
    if (i >= (long long)N_NODES * (HIDDEN / 4)) return;
    float4 a = ((const float4*)g_agg)[i];
    float4 h = ((float4*)g_h)[i];
    a.x = elu1(a.x + h.x);
    a.y = elu1(a.y + h.y);
    a.z = elu1(a.z + h.z);
    a.w = elu1(a.w + h.w);
    ((float4*)g_h)[i] = a;
}

// ---------------- output LN + ELU + write node_emb + pool ----------------
__global__ void ln_out_kernel(const float* __restrict__ lg,
                              const float* __restrict__ lb,
                              const int* __restrict__ batch,
                              float* __restrict__ node_out) {
    int n = blockIdx.x;
    int j = threadIdx.x;
    __shared__ float red[HIDDEN];
    float y = g_hp[(long long)n * HIDDEN + j];
    red[j] = y; __syncthreads();
    for (int s = HIDDEN / 2; s > 0; s >>= 1) { if (j < s) red[j] += red[j + s]; __syncthreads(); }
    float mu = red[0] * (1.f / HIDDEN);
    __syncthreads();
    float d = y - mu;
    red[j] = d * d; __syncthreads();
    for (int s = HIDDEN / 2; s > 0; s >>= 1) { if (j < s) red[j] += red[j + s]; __syncthreads(); }
    float var = red[0] * (1.f / HIDDEN);
    float v = elu1(d * rsqrtf(var + 1e-5f) * lg[j] + lb[j]);
    node_out[(long long)n * HIDDEN + j] = v;
    int b = batch[n];
    atomicAdd(&g_pool[b * HIDDEN + j], v);
    if (j == 0) atomicAdd(&g_cnt[b], 1.0f);
}

// ---------------- graph mean pool output ----------------
__global__ void graph_out_kernel(float* __restrict__ out) {
    int i = blockIdx.x * blockDim.x + threadIdx.x;
    if (i < NUM_GRAPHS * HIDDEN) out[i] = g_pool[i] / fmaxf(g_cnt[i >> 8], 1.0f);
}

// ---------------- launch ----------------
extern "C" void kernel_launch(void* const* d_in, const int* in_sizes, int n_in,
                              void* d_out, int out_size) {
    const float* x          = (const float*)d_in[0];
    const int*   edge_index = (const int*)d_in[1];   // int64 in reference -> int32 in harness
    const float* edge_attr  = (const float*)d_in[2];
    const int*   batch      = (const int*)d_in[3];
    const float* W_in       = (const float*)d_in[4];
    const float* b_in       = (const float*)d_in[5];
    const float* ln_in_g    = (const float*)d_in[6];
    const float* ln_in_b    = (const float*)d_in[7];
    const float* W_gat      = (const float*)d_in[8];   // [3,256,256]
    const float* b_gat      = (const float*)d_in[9];   // [3,256]
    const float* W_e        = (const float*)d_in[10];  // [3,3,256]
    const float* a_src      = (const float*)d_in[11];  // [3,4,64]
    const float* a_dst      = (const float*)d_in[12];
    const float* a_edge     = (const float*)d_in[13];
    const float* W_out      = (const float*)d_in[14];
    const float* b_out      = (const float*)d_in[15];
    const float* ln_out_g   = (const float*)d_in[16];
    const float* ln_out_b   = (const float*)d_in[17];

    float* out = (float*)d_out;

    float *hp_, *h_, *agg_;
    cudaGetSymbolAddress((void**)&h_, g_h);
    cudaGetSymbolAddress((void**)&hp_, g_hp);
    cudaGetSymbolAddress((void**)&agg_, g_agg);

    // graph_emb first, node_emb after — guard against an output layout with only graph_emb
    long long node_off = (long long)out_size - (long long)N_NODES * HIDDEN;
    float* node_out = (node_off >= 0) ? out + node_off : agg_;

    // init pooling accumulators
    init_pool_kernel<<<(NUM_GRAPHS * HIDDEN + 255) / 256, 256>>>();

    // input projection
    input_proj_kernel<<<N_NODES, HIDDEN>>>(x, W_in, b_in, ln_in_g, ln_in_b);

    dim3 gemm_grid(2, (N_NODES + 127) / 128);
    int score_blocks = (N_NODES * HEADS * 32 + 255) / 256;
    int edge_blocks = (N_EDGES + 255) / 256;
    int msg_blocks = (N_EDGES * 32 + 255) / 256;

    for (int l = 0; l < LAYERS; l++) {
        const float* Wl  = W_gat + (long long)l * HIDDEN * HIDDEN;
        const float* bl  = b_gat + l * HIDDEN;
        const float* Wel = W_e + l * 3 * HIDDEN;
        const float* asl = a_src + l * HEADS * HEAD_DIM;
        const float* adl = a_dst + l * HEADS * HEAD_DIM;
        const float* ael = a_edge + l * HEADS * HEAD_DIM;

        sgemm_bias_kernel<<<gemm_grid, 256>>>(h_, Wl, bl, hp_, N_NODES);
        compute_c_kernel<<<1, 32>>>(Wel, ael);
        node_score_kernel<<<score_blocks, 256>>>(asl, adl);
        edge_logit_kernel<<<edge_blocks, 256>>>(edge_index, edge_attr);
        edge_exp_kernel<<<edge_blocks, 256>>>(edge_index);
        edge_msg_kernel<<<msg_blocks, 256>>>(edge_index);
        combine_kernel<<<(N_NODES * (HIDDEN / 4) + 255) / 256, 256>>>();
    }

    // output projection + LN + ELU + pooling
    sgemm_bias_kernel<<<gemm_grid, 256>>>(h_, W_out, b_out, hp_, N_NODES);
    ln_out_kernel<<<N_NODES, HIDDEN>>>(ln_out_g, ln_out_b, batch, node_out);
    graph_out_kernel<<<(NUM_GRAPHS * HIDDEN + 255) / 256, 256>>>(out);
}

// round 5
// speedup vs baseline: 1.8779x; 1.8779x over previous
#include <cuda_runtime.h>
#include <cuda_bf16.h>
#include <math.h>

#define N_NODES 50000
#define N_EDGES 800000
#define HIDDEN  256
#define HEADS   4
#define HEAD_DIM 64
#define LAYERS  3
#define NUM_GRAPHS 64
#define NEG_SLOPE 0.2f

// ---------------- scratch (device globals; no allocation allowed) ----------------
__device__ float g_h   [(long long)N_NODES * HIDDEN];
__device__ float g_hp  [(long long)N_NODES * HIDDEN];
__device__ float g_ss  [N_NODES * HEADS];
__device__ float g_sd  [N_NODES * HEADS];
__device__ float g_c   [HEADS * 3];
__device__ float g_pool[NUM_GRAPHS * HIDDEN];
__device__ float g_cnt [NUM_GRAPHS];
// CSR scratch
__device__ int    g_deg[N_NODES];
__device__ int    g_off[N_NODES + 1];
__device__ int    g_cur[N_NODES];
__device__ int    g_csr_src[N_EDGES];
__device__ float4 g_csr_att[N_EDGES];

// ---------------- helpers ----------------
__device__ __forceinline__ float elu1(float v) {
    return v > 0.f ? v : expm1f(v);
}

// ---------------- init: pooling accumulators + degree histogram ----------------
__global__ void init_kernel() {
    int i = blockIdx.x * blockDim.x + threadIdx.x;
    if (i < NUM_GRAPHS * HIDDEN) g_pool[i] = 0.f;
    if (i < NUM_GRAPHS) g_cnt[i] = 0.f;
    if (i < N_NODES) g_deg[i] = 0;
}

// ---------------- input projection + LN + ELU ----------------
__global__ void input_proj_kernel(const float* __restrict__ x,
                                  const float* __restrict__ Win,
                                  const float* __restrict__ bin,
                                  const float* __restrict__ lg,
                                  const float* __restrict__ lb) {
    int n = blockIdx.x;
    int j = threadIdx.x;
    __shared__ float xs[8];
    __shared__ float red[HIDDEN];
    if (j < 8) xs[j] = x[n * 8 + j];
    __syncthreads();
    float y = bin[j];
    #pragma unroll
    for (int k = 0; k < 8; k++) y += xs[k] * Win[k * HIDDEN + j];
    red[j] = y; __syncthreads();
    for (int s = HIDDEN / 2; s > 0; s >>= 1) { if (j < s) red[j] += red[j + s]; __syncthreads(); }
    float mu = red[0] * (1.f / HIDDEN);
    __syncthreads();
    float d = y - mu;
    red[j] = d * d; __syncthreads();
    for (int s = HIDDEN / 2; s > 0; s >>= 1) { if (j < s) red[j] += red[j + s]; __syncthreads(); }
    float var = red[0] * (1.f / HIDDEN);
    float v = d * rsqrtf(var + 1e-5f) * lg[j] + lb[j];
    g_h[(long long)n * HIDDEN + j] = elu1(v);
}

// ---------------- CSR build ----------------
__global__ void hist_kernel(const int* __restrict__ ei) {
    int e = blockIdx.x * blockDim.x + threadIdx.x;
    if (e >= N_EDGES) return;
    atomicAdd(&g_deg[ei[N_EDGES + e]], 1);
}

__global__ void scan_kernel() {
    __shared__ int sh[1024];
    __shared__ int carry_s;
    int t = threadIdx.x;
    if (t == 0) carry_s = 0;
    __syncthreads();
    for (int base = 0; base < N_NODES; base += 1024) {
        int idx = base + t;
        int v = (idx < N_NODES) ? g_deg[idx] : 0;
        sh[t] = v;
        __syncthreads();
        #pragma unroll
        for (int o = 1; o < 1024; o <<= 1) {
            int y = (t >= o) ? sh[t - o] : 0;
            __syncthreads();
            sh[t] += y;
            __syncthreads();
        }
        int incl = sh[t];
        int c = carry_s;
        if (idx < N_NODES) {
            int ex = c + incl - v;
            g_off[idx] = ex;
            g_cur[idx] = ex;
        }
        __syncthreads();
        if (t == 0) carry_s = c + sh[1023];
        __syncthreads();
    }
    if (t == 0) g_off[N_NODES] = carry_s;
}

__global__ void scatter_kernel(const int* __restrict__ ei,
                               const float* __restrict__ ea) {
    int e = blockIdx.x * blockDim.x + threadIdx.x;
    if (e >= N_EDGES) return;
    int s = ei[e];
    int d = ei[N_EDGES + e];
    int pos = atomicAdd(&g_cur[d], 1);
    g_csr_src[pos] = s;
    g_csr_att[pos] = make_float4(ea[e * 3 + 0], ea[e * 3 + 1], ea[e * 3 + 2], 0.f);
}

// ---------------- SGEMM: C[M,256] = A[M,256] @ B[256,256] + bias ----------------
__global__ void sgemm_bias_kernel(const float* __restrict__ A,
                                  const float* __restrict__ B,
                                  const float* __restrict__ bias,
                                  float* __restrict__ C,
                                  int M) {
    const int Nn = 256, K = 256;
    const int BM = 128, BN = 128, BK = 8, TM = 8, TN = 8;
    __shared__ float As[BK][BM];
    __shared__ float Bs[BK][BN];
    int tid = threadIdx.x;
    int cRow = blockIdx.y, cCol = blockIdx.x;
    int tRow = tid / (BN / TN);
    int tCol = tid % (BN / TN);
    float acc[TM][TN];
    #pragma unroll
    for (int i = 0; i < TM; i++)
        #pragma unroll
        for (int j = 0; j < TN; j++) acc[i][j] = 0.f;
    float regM[TM], regN[TN];

    int aRow = tid >> 1;
    int aCol = (tid & 1) * 4;
    int bRow = tid >> 5;
    int bCol = (tid & 31) * 4;

    const float* Ab = A + (long long)cRow * BM * K;
    const float* Bb = B + cCol * BN;
    int mRow = cRow * BM + aRow;

    for (int kt = 0; kt < K; kt += BK) {
        float4 av = (mRow < M) ? *(const float4*)&Ab[aRow * K + kt + aCol]
                               : make_float4(0.f, 0.f, 0.f, 0.f);
        As[aCol + 0][aRow] = av.x;
        As[aCol + 1][aRow] = av.y;
        As[aCol + 2][aRow] = av.z;
        As[aCol + 3][aRow] = av.w;
        float4 bv = *(const float4*)&Bb[(long long)(kt + bRow) * Nn + bCol];
        *(float4*)&Bs[bRow][bCol] = bv;
        __syncthreads();
        #pragma unroll
        for (int k = 0; k < BK; k++) {
            #pragma unroll
            for (int i = 0; i < TM; i++) regM[i] = As[k][tRow * TM + i];
            #pragma unroll
            for (int j = 0; j < TN; j++) regN[j] = Bs[k][tCol * TN + j];
            #pragma unroll
            for (int i = 0; i < TM; i++)
                #pragma unroll
                for (int j = 0; j < TN; j++) acc[i][j] += regM[i] * regN[j];
        }
        __syncthreads();
    }
    #pragma unroll
    for (int i = 0; i < TM; i++) {
        int row = cRow * BM + tRow * TM + i;
        if (row < M) {
            #pragma unroll
            for (int j = 0; j < TN; j += 4) {
                int col = cCol * BN + tCol * TN + j;
                float4 v;
                v.x = acc[i][j + 0] + bias[col + 0];
                v.y = acc[i][j + 1] + bias[col + 1];
                v.z = acc[i][j + 2] + bias[col + 2];
                v.w = acc[i][j + 3] + bias[col + 3];
                *(float4*)&C[(long long)row * Nn + col] = v;
            }
        }
    }
}

// ---------------- node attention scores (+ per-layer c precompute in block 0) ----------------
__global__ void node_score_kernel(const float* __restrict__ as_,
                                  const float* __restrict__ ad_,
                                  const float* __restrict__ We,
                                  const float* __restrict__ ae) {
    if (blockIdx.x == 0 && threadIdx.x < HEADS * 3) {
        int i = threadIdx.x;
        int hh = i / 3, k = i % 3;
        float s = 0.f;
        for (int d = 0; d < HEAD_DIM; d++)
            s += We[k * HIDDEN + hh * HEAD_DIM + d] * ae[hh * HEAD_DIM + d];
        g_c[i] = s;
    }
    int gw = (blockIdx.x * blockDim.x + threadIdx.x) >> 5;
    int lane = threadIdx.x & 31;
    if (gw >= N_NODES * HEADS) return;
    int n = gw >> 2, hh = gw & 3;
    const float* row = g_hp + (long long)n * HIDDEN + hh * HEAD_DIM;
    float v0 = row[lane], v1 = row[lane + 32];
    float s = v0 * as_[hh * HEAD_DIM + lane] + v1 * as_[hh * HEAD_DIM + lane + 32];
    float t = v0 * ad_[hh * HEAD_DIM + lane] + v1 * ad_[hh * HEAD_DIM + lane + 32];
    #pragma unroll
    for (int o = 16; o > 0; o >>= 1) {
        s += __shfl_xor_sync(0xFFFFFFFFu, s, o);
        t += __shfl_xor_sync(0xFFFFFFFFu, t, o);
    }
    if (lane == 0) {
        g_ss[gw] = s;
        g_sd[gw] = t;
    }
}

// ---------------- fused GAT layer: softmax + message agg + residual + ELU ----------------
// one warp per destination node; lane owns 8 columns (one head)
__global__ void gat_fused_kernel() {
    int gw = (blockIdx.x * blockDim.x + threadIdx.x) >> 5;
    int lane = threadIdx.x & 31;
    if (gw >= N_NODES) return;
    int n = gw;
    int r0 = g_off[n], r1 = g_off[n + 1];
    int h = lane >> 3;                       // head for this lane's columns
    long long hb = (long long)n * HIDDEN + lane * 8;
    float4 hv0 = *(const float4*)&g_h[hb];
    float4 hv1 = *(const float4*)&g_h[hb + 4];

    if (r0 == r1) {                          // isolated node: out = elu(h)
        hv0.x = elu1(hv0.x); hv0.y = elu1(hv0.y); hv0.z = elu1(hv0.z); hv0.w = elu1(hv0.w);
        hv1.x = elu1(hv1.x); hv1.y = elu1(hv1.y); hv1.z = elu1(hv1.z); hv1.w = elu1(hv1.w);
        *(float4*)&g_h[hb] = hv0;
        *(float4*)&g_h[hb + 4] = hv1;
        return;
    }

    float sd0 = g_sd[n * 4 + 0], sd1 = g_sd[n * 4 + 1];
    float sd2 = g_sd[n * 4 + 2], sd3 = g_sd[n * 4 + 3];
    float c00 = g_c[0], c01 = g_c[1],  c02 = g_c[2];
    float c10 = g_c[3], c11 = g_c[4],  c12 = g_c[5];
    float c20 = g_c[6], c21 = g_c[7],  c22 = g_c[8];
    float c30 = g_c[9], c31 = g_c[10], c32 = g_c[11];

    // pass A: per-head max over incoming edges (lanes parallel over edges)
    float m0 = -INFINITY, m1 = -INFINITY, m2 = -INFINITY, m3 = -INFINITY;
    for (int i = r0 + lane; i < r1; i += 32) {
        int s = g_csr_src[i];
        float4 at = g_csr_att[i];
        float l0 = g_ss[s * 4 + 0] + sd0 + at.x * c00 + at.y * c01 + at.z * c02;
        float l1 = g_ss[s * 4 + 1] + sd1 + at.x * c10 + at.y * c11 + at.z * c12;
        float l2 = g_ss[s * 4 + 2] + sd2 + at.x * c20 + at.y * c21 + at.z * c22;
        float l3 = g_ss[s * 4 + 3] + sd3 + at.x * c30 + at.y * c31 + at.z * c32;
        l0 = l0 > 0.f ? l0 : NEG_SLOPE * l0;
        l1 = l1 > 0.f ? l1 : NEG_SLOPE * l1;
        l2 = l2 > 0.f ? l2 : NEG_SLOPE * l2;
        l3 = l3 > 0.f ? l3 : NEG_SLOPE * l3;
        m0 = fmaxf(m0, l0); m1 = fmaxf(m1, l1);
        m2 = fmaxf(m2, l2); m3 = fmaxf(m3, l3);
    }
    #pragma unroll
    for (int o = 16; o > 0; o >>= 1) {
        m0 = fmaxf(m0, __shfl_xor_sync(0xFFFFFFFFu, m0, o));
        m1 = fmaxf(m1, __shfl_xor_sync(0xFFFFFFFFu, m1, o));
        m2 = fmaxf(m2, __shfl_xor_sync(0xFFFFFFFFu, m2, o));
        m3 = fmaxf(m3, __shfl_xor_sync(0xFFFFFFFFu, m3, o));
    }
    float mh  = h == 0 ? m0 : (h == 1 ? m1 : (h == 2 ? m2 : m3));
    float sdh = h == 0 ? sd0 : (h == 1 ? sd1 : (h == 2 ? sd2 : sd3));
    float ch0 = h == 0 ? c00 : (h == 1 ? c10 : (h == 2 ? c20 : c30));
    float ch1 = h == 0 ? c01 : (h == 1 ? c11 : (h == 2 ? c21 : c31));
    float ch2 = h == 0 ? c02 : (h == 1 ? c12 : (h == 2 ? c22 : c32));

    // pass B: accumulate denom + weighted messages (warp-parallel over columns)
    float4 a0 = make_float4(0.f, 0.f, 0.f, 0.f);
    float4 a1 = make_float4(0.f, 0.f, 0.f, 0.f);
    float den = 0.f;
    for (int i = r0; i < r1; i++) {
        int s = g_csr_src[i];
        float4 at = g_csr_att[i];
        float l = g_ss[s * 4 + h] + sdh + at.x * ch0 + at.y * ch1 + at.z * ch2;
        l = l > 0.f ? l : NEG_SLOPE * l;
        float w = expf(l - mh);
        den += w;
        const float* row = &g_hp[(long long)s * HIDDEN + lane * 8];
        float4 v0 = *(const float4*)row;
        float4 v1 = *(const float4*)(row + 4);
        a0.x += w * v0.x; a0.y += w * v0.y; a0.z += w * v0.z; a0.w += w * v0.w;
        a1.x += w * v1.x; a1.y += w * v1.y; a1.z += w * v1.z; a1.w += w * v1.w;
    }
    float inv = 1.f / fmaxf(den, 1e-16f);
    hv0.x = elu1(a0.x * inv + hv0.x); hv0.y = elu1(a0.y * inv + hv0.y);
    hv0.z = elu1(a0.z * inv + hv0.z); hv0.w = elu1(a0.w * inv + hv0.w);
    hv1.x = elu1(a1.x * inv + hv1.x); hv1.y = elu1(a1.y * inv + hv1.y);
    hv1.z = elu1(a1.z * inv + hv1.z); hv1.w = elu1(a1.w * inv + hv1.w);
    *(float4*)&g_h[hb] = hv0;
    *(float4*)&g_h[hb + 4] = hv1;
}

// ---------------- output LN + ELU + write node_emb + pool ----------------
__global__ void ln_out_kernel(const float* __restrict__ lg,
                              const float* __restrict__ lb,
                              const int* __restrict__ batch,
                              float* __restrict__ node_out) {
    int n = blockIdx.x;
    int j = threadIdx.x;
    __shared__ float red[HIDDEN];
    float y = g_hp[(long long)n * HIDDEN + j];
    red[j] = y; __syncthreads();
    for (int s = HIDDEN / 2; s > 0; s >>= 1) { if (j < s) red[j] += red[j + s]; __syncthreads(); }
    float mu = red[0] * (1.f / HIDDEN);
    __syncthreads();
    float d = y - mu;
    red[j] = d * d; __syncthreads();
    for (int s = HIDDEN / 2; s > 0; s >>= 1) { if (j < s) red[j] += red[j + s]; __syncthreads(); }
    float var = red[0] * (1.f / HIDDEN);
    float v = elu1(d * rsqrtf(var + 1e-5f) * lg[j] + lb[j]);
    node_out[(long long)n * HIDDEN + j] = v;
    int b = batch[n];
    atomicAdd(&g_pool[b * HIDDEN + j], v);
    if (j == 0) atomicAdd(&g_cnt[b], 1.0f);
}

// ---------------- graph mean pool output ----------------
__global__ void graph_out_kernel(float* __restrict__ out) {
    int i = blockIdx.x * blockDim.x + threadIdx.x;
    if (i < NUM_GRAPHS * HIDDEN) out[i] = g_pool[i] / fmaxf(g_cnt[i >> 8], 1.0f);
}

// ---------------- launch ----------------
extern "C" void kernel_launch(void* const* d_in, const int* in_sizes, int n_in,
                              void* d_out, int out_size) {
    const float* x          = (const float*)d_in[0];
    const int*   edge_index = (const int*)d_in[1];   // int64 in reference -> int32 in harness
    const float* edge_attr  = (const float*)d_in[2];
    const int*   batch      = (const int*)d_in[3];
    const float* W_in       = (const float*)d_in[4];
    const float* b_in       = (const float*)d_in[5];
    const float* ln_in_g    = (const float*)d_in[6];
    const float* ln_in_b    = (const float*)d_in[7];
    const float* W_gat      = (const float*)d_in[8];   // [3,256,256]
    const float* b_gat      = (const float*)d_in[9];   // [3,256]
    const float* W_e        = (const float*)d_in[10];  // [3,3,256]
    const float* a_src      = (const float*)d_in[11];  // [3,4,64]
    const float* a_dst      = (const float*)d_in[12];
    const float* a_edge     = (const float*)d_in[13];
    const float* W_out      = (const float*)d_in[14];
    const float* b_out      = (const float*)d_in[15];
    const float* ln_out_g   = (const float*)d_in[16];
    const float* ln_out_b   = (const float*)d_in[17];

    float* out = (float*)d_out;

    float *hp_, *h_;
    cudaGetSymbolAddress((void**)&h_, g_h);
    cudaGetSymbolAddress((void**)&hp_, g_hp);

    long long node_off = (long long)out_size - (long long)N_NODES * HIDDEN;
    float* node_out = (node_off >= 0) ? out + node_off : hp_;

    // init + input projection + CSR build (dst is launch-invariant)
    init_kernel<<<(N_NODES + 255) / 256, 256>>>();
    input_proj_kernel<<<N_NODES, HIDDEN>>>(x, W_in, b_in, ln_in_g, ln_in_b);
    hist_kernel<<<(N_EDGES + 255) / 256, 256>>>(edge_index);
    scan_kernel<<<1, 1024>>>();
    scatter_kernel<<<(N_EDGES + 255) / 256, 256>>>(edge_index, edge_attr);

    dim3 gemm_grid(2, (N_NODES + 127) / 128);
    int score_blocks = (N_NODES * HEADS * 32 + 255) / 256;
    int gat_blocks = (N_NODES * 32 + 255) / 256;

    for (int l = 0; l < LAYERS; l++) {
        const float* Wl  = W_gat + (long long)l * HIDDEN * HIDDEN;
        const float* bl  = b_gat + l * HIDDEN;
        const float* Wel = W_e + l * 3 * HIDDEN;
        const float* asl = a_src + l * HEADS * HEAD_DIM;
        const float* adl = a_dst + l * HEADS * HEAD_DIM;
        const float* ael = a_edge + l * HEADS * HEAD_DIM;

        sgemm_bias_kernel<<<gemm_grid, 256>>>(h_, Wl, bl, hp_, N_NODES);
        node_score_kernel<<<score_blocks, 256>>>(asl, adl, Wel, ael);
        gat_fused_kernel<<<gat_blocks, 256>>>();
    }

    // output projection + LN + ELU + pooling
    sgemm_bias_kernel<<<gemm_grid, 256>>>(h_, W_out, b_out, hp_, N_NODES);
    ln_out_kernel<<<N_NODES, HIDDEN>>>(ln_out_g, ln_out_b, batch, node_out);
    graph_out_kernel<<<(NUM_GRAPHS * HIDDEN + 255) / 256, 256>>>(out);
}

// round 7
// speedup vs baseline: 3.0341x; 1.6157x over previous
#include <cuda_runtime.h>
#include <cuda_bf16.h>
#include <math.h>
#include <stdint.h>

#define N_NODES 50000
#define N_EDGES 800000
#define HIDDEN  256
#define HEADS   4
#define HEAD_DIM 64
#define LAYERS  3
#define NUM_GRAPHS 64
#define NEG_SLOPE 0.2f

// ---------------- scratch (device globals; no allocation allowed) ----------------
__device__ float g_h   [(long long)N_NODES * HIDDEN];
__device__ float g_hp  [(long long)N_NODES * HIDDEN];
__device__ float g_ss  [N_NODES * HEADS];
__device__ float g_sd  [N_NODES * HEADS];
__device__ float g_c   [HEADS * 3];
__device__ float g_pool[NUM_GRAPHS * HIDDEN];
__device__ float g_cnt [NUM_GRAPHS];
// CSR scratch
__device__ int    g_deg[N_NODES];
__device__ int    g_off[N_NODES + 1];
__device__ int    g_cur[N_NODES];
__device__ int    g_csr_src[N_EDGES];
__device__ float4 g_csr_att[N_EDGES];

// ---------------- helpers ----------------
__device__ __forceinline__ float elu1(float v) {
    return v > 0.f ? v : expm1f(v);
}

__device__ __forceinline__ uint32_t f2tf32(float x) {
    uint32_t u;
    asm("cvt.rna.tf32.f32 %0, %1;" : "=r"(u) : "f"(x));
    return u;
}

// ---------------- init: pooling accumulators + degree histogram ----------------
__global__ void init_kernel() {
    int i = blockIdx.x * blockDim.x + threadIdx.x;
    if (i < NUM_GRAPHS * HIDDEN) g_pool[i] = 0.f;
    if (i < NUM_GRAPHS) g_cnt[i] = 0.f;
    if (i < N_NODES) g_deg[i] = 0;
}

// ---------------- block LN reduce helper (256 threads) ----------------
__device__ __forceinline__ float block_sum_256(float v, float* ws) {
    int lane = threadIdx.x & 31, wid = threadIdx.x >> 5;
    #pragma unroll
    for (int o = 16; o > 0; o >>= 1) v += __shfl_xor_sync(0xFFFFFFFFu, v, o);
    if (lane == 0) ws[wid] = v;
    __syncthreads();
    float s = ws[0] + ws[1] + ws[2] + ws[3] + ws[4] + ws[5] + ws[6] + ws[7];
    __syncthreads();
    return s;
}

// ---------------- input projection + LN + ELU ----------------
__global__ void input_proj_kernel(const float* __restrict__ x,
                                  const float* __restrict__ Win,
                                  const float* __restrict__ bin,
                                  const float* __restrict__ lg,
                                  const float* __restrict__ lb) {
    int n = blockIdx.x;
    int j = threadIdx.x;
    __shared__ float xs[8];
    __shared__ float ws[8];
    if (j < 8) xs[j] = x[n * 8 + j];
    __syncthreads();
    float y = bin[j];
    #pragma unroll
    for (int k = 0; k < 8; k++) y += xs[k] * Win[k * HIDDEN + j];
    float mu = block_sum_256(y, ws) * (1.f / HIDDEN);
    float d = y - mu;
    float var = block_sum_256(d * d, ws) * (1.f / HIDDEN);
    float v = d * rsqrtf(var + 1e-5f) * lg[j] + lb[j];
    g_h[(long long)n * HIDDEN + j] = elu1(v);
}

// ---------------- CSR build ----------------
__global__ void hist_kernel(const int* __restrict__ ei) {
    int e = blockIdx.x * blockDim.x + threadIdx.x;
    if (e >= N_EDGES) return;
    atomicAdd(&g_deg[ei[N_EDGES + e]], 1);
}

__global__ void scan_fast_kernel() {
    const int CH = (N_NODES + 1023) / 1024;   // 49
    int t = threadIdx.x;
    int start = t * CH;
    int end = min(start + CH, N_NODES);
    int sum = 0;
    for (int i = start; i < end; i++) sum += g_deg[i];
    __shared__ int warp_tot[32];
    int lane = t & 31, wid = t >> 5;
    int v = sum;
    #pragma unroll
    for (int o = 1; o < 32; o <<= 1) {
        int y = __shfl_up_sync(0xFFFFFFFFu, v, o);
        if (lane >= o) v += y;
    }
    if (lane == 31) warp_tot[wid] = v;
    __syncthreads();
    if (wid == 0) {
        int w = warp_tot[lane];
        #pragma unroll
        for (int o = 1; o < 32; o <<= 1) {
            int y = __shfl_up_sync(0xFFFFFFFFu, w, o);
            if (lane >= o) w += y;
        }
        warp_tot[lane] = w;
    }
    __syncthreads();
    int excl = v - sum + (wid > 0 ? warp_tot[wid - 1] : 0);
    int run = excl;
    for (int i = start; i < end; i++) {
        g_off[i] = run;
        g_cur[i] = run;
        run += g_deg[i];
    }
    if (t == 1023) g_off[N_NODES] = run;
}

__global__ void scatter_kernel(const int* __restrict__ ei,
                               const float* __restrict__ ea) {
    int e = blockIdx.x * blockDim.x + threadIdx.x;
    if (e >= N_EDGES) return;
    int s = ei[e];
    int d = ei[N_EDGES + e];
    int pos = atomicAdd(&g_cur[d], 1);
    g_csr_src[pos] = s;
    g_csr_att[pos] = make_float4(ea[e * 3 + 0], ea[e * 3 + 1], ea[e * 3 + 2], 0.f);
}

// ---------------- mma.sync tf32 GEMM: C[M,256] = A[M,256] @ B[256,256] + bias ----------------
// CTA 128x128, 8 warps (2M x 4N), warp tile 64x32 = 4x4 m16n8k8 fragments.
#define GBM 128
#define GBN 128
#define GBK 32
#define A_STRIDE 36
#define B_STRIDE 136

__global__ void __launch_bounds__(256, 2)
gemm_mma_kernel(const float* __restrict__ A,
                const float* __restrict__ B,
                const float* __restrict__ bias,
                float* __restrict__ C,
                int M) {
    __shared__ uint32_t As[GBM * A_STRIDE];   // [row][k] tf32 bits
    __shared__ uint32_t Bs[GBK * B_STRIDE];   // [k][n]  tf32 bits

    int tid = threadIdx.x;
    int warp = tid >> 5;
    int lane = tid & 31;
    int wm = warp >> 2;           // 0..1
    int wn = warp & 3;            // 0..3
    int cCol = blockIdx.x;        // n-half (0..1)
    int cRow = blockIdx.y;

    float acc[4][4][4];
    #pragma unroll
    for (int i = 0; i < 4; i++)
        #pragma unroll
        for (int j = 0; j < 4; j++)
            #pragma unroll
            for (int r = 0; r < 4; r++) acc[i][j][r] = 0.f;

    int lr = lane >> 2;           // 0..7
    int lc = lane & 3;            // 0..3

    for (int kc = 0; kc < 256 / GBK; kc++) {
        // load A chunk: 128 rows x 32 k
        #pragma unroll
        for (int i = 0; i < 4; i++) {
            int s = tid + i * 256;            // 1024 float4 slots
            int row = s >> 3;
            int col4 = (s & 7) * 4;
            int grow = cRow * GBM + row;
            float4 av = (grow < M) ? *(const float4*)&A[(long long)grow * 256 + kc * GBK + col4]
                                   : make_float4(0.f, 0.f, 0.f, 0.f);
            uint4 tv = make_uint4(f2tf32(av.x), f2tf32(av.y), f2tf32(av.z), f2tf32(av.w));
            *(uint4*)&As[row * A_STRIDE + col4] = tv;
        }
        // load B chunk: 32 k x 128 n
        #pragma unroll
        for (int i = 0; i < 4; i++) {
            int s = tid + i * 256;            // 1024 float4 slots
            int k = s >> 5;
            int n4 = (s & 31) * 4;
            float4 bv = *(const float4*)&B[(long long)(kc * GBK + k) * 256 + cCol * GBN + n4];
            uint4 tv = make_uint4(f2tf32(bv.x), f2tf32(bv.y), f2tf32(bv.z), f2tf32(bv.w));
            *(uint4*)&Bs[k * B_STRIDE + n4] = tv;
        }
        __syncthreads();

        #pragma unroll
        for (int ks = 0; ks < GBK / 8; ks++) {
            int k0 = ks * 8;
            // B fragments for the 4 n-tiles
            uint32_t bf[4][2];
            #pragma unroll
            for (int nt = 0; nt < 4; nt++) {
                int nb = wn * 32 + nt * 8 + lr;
                bf[nt][0] = Bs[(k0 + lc) * B_STRIDE + nb];
                bf[nt][1] = Bs[(k0 + lc + 4) * B_STRIDE + nb];
            }
            #pragma unroll
            for (int mt = 0; mt < 4; mt++) {
                int rm = wm * 64 + mt * 16;
                uint32_t a0 = As[(rm + lr) * A_STRIDE + k0 + lc];
                uint32_t a1 = As[(rm + lr + 8) * A_STRIDE + k0 + lc];
                uint32_t a2 = As[(rm + lr) * A_STRIDE + k0 + lc + 4];
                uint32_t a3 = As[(rm + lr + 8) * A_STRIDE + k0 + lc + 4];
                #pragma unroll
                for (int nt = 0; nt < 4; nt++) {
                    asm volatile(
                        "mma.sync.aligned.m16n8k8.row.col.f32.tf32.tf32.f32 "
                        "{%0,%1,%2,%3}, {%4,%5,%6,%7}, {%8,%9}, {%0,%1,%2,%3};"
                        : "+f"(acc[mt][nt][0]), "+f"(acc[mt][nt][1]),
                          "+f"(acc[mt][nt][2]), "+f"(acc[mt][nt][3])
                        : "r"(a0), "r"(a1), "r"(a2), "r"(a3),
                          "r"(bf[nt][0]), "r"(bf[nt][1]));
                }
            }
        }
        __syncthreads();
    }

    // epilogue: direct stores (+bias). c0,c1 -> row, c2,c3 -> row+8, cols 2*lc, 2*lc+1
    #pragma unroll
    for (int mt = 0; mt < 4; mt++) {
        int row0 = cRow * GBM + wm * 64 + mt * 16 + lr;
        #pragma unroll
        for (int nt = 0; nt < 4; nt++) {
            int col = cCol * GBN + wn * 32 + nt * 8 + lc * 2;
            float b0 = bias[col], b1 = bias[col + 1];
            if (row0 < M) {
                float2 v0 = make_float2(acc[mt][nt][0] + b0, acc[mt][nt][1] + b1);
                *(float2*)&C[(long long)row0 * 256 + col] = v0;
            }
            if (row0 + 8 < M) {
                float2 v1 = make_float2(acc[mt][nt][2] + b0, acc[mt][nt][3] + b1);
                *(float2*)&C[(long long)(row0 + 8) * 256 + col] = v1;
            }
        }
    }
}

// ---------------- node attention scores (+ per-layer c precompute in block 0) ----------------
__global__ void node_score_kernel(const float* __restrict__ as_,
                                  const float* __restrict__ ad_,
                                  const float* __restrict__ We,
                                  const float* __restrict__ ae) {
    if (blockIdx.x == 0 && threadIdx.x < HEADS * 3) {
        int i = threadIdx.x;
        int hh = i / 3, k = i % 3;
        float s = 0.f;
        for (int d = 0; d < HEAD_DIM; d++)
            s += We[k * HIDDEN + hh * HEAD_DIM + d] * ae[hh * HEAD_DIM + d];
        g_c[i] = s;
    }
    int gw = (blockIdx.x * blockDim.x + threadIdx.x) >> 5;
    int lane = threadIdx.x & 31;
    if (gw >= N_NODES * HEADS) return;
    int n = gw >> 2, hh = gw & 3;
    const float* row = g_hp + (long long)n * HIDDEN + hh * HEAD_DIM;
    float v0 = row[lane], v1 = row[lane + 32];
    float s = v0 * as_[hh * HEAD_DIM + lane] + v1 * as_[hh * HEAD_DIM + lane + 32];
    float t = v0 * ad_[hh * HEAD_DIM + lane] + v1 * ad_[hh * HEAD_DIM + lane + 32];
    #pragma unroll
    for (int o = 16; o > 0; o >>= 1) {
        s += __shfl_xor_sync(0xFFFFFFFFu, s, o);
        t += __shfl_xor_sync(0xFFFFFFFFu, t, o);
    }
    if (lane == 0) {
        g_ss[gw] = s;
        g_sd[gw] = t;
    }
}

// ---------------- fused GAT layer: softmax + message agg + residual + ELU ----------------
__global__ void gat_fused_kernel() {
    int gw = (blockIdx.x * blockDim.x + threadIdx.x) >> 5;
    int lane = threadIdx.x & 31;
    if (gw >= N_NODES) return;
    int n = gw;
    int r0 = g_off[n], r1 = g_off[n + 1];
    int h = lane >> 3;
    long long hb = (long long)n * HIDDEN + lane * 8;
    float4 hv0 = *(const float4*)&g_h[hb];
    float4 hv1 = *(const float4*)&g_h[hb + 4];

    if (r0 == r1) {
        hv0.x = elu1(hv0.x); hv0.y = elu1(hv0.y); hv0.z = elu1(hv0.z); hv0.w = elu1(hv0.w);
        hv1.x = elu1(hv1.x); hv1.y = elu1(hv1.y); hv1.z = elu1(hv1.z); hv1.w = elu1(hv1.w);
        *(float4*)&g_h[hb] = hv0;
        *(float4*)&g_h[hb + 4] = hv1;
        return;
    }

    float sd0 = g_sd[n * 4 + 0], sd1 = g_sd[n * 4 + 1];
    float sd2 = g_sd[n * 4 + 2], sd3 = g_sd[n * 4 + 3];
    float c00 = g_c[0], c01 = g_c[1],  c02 = g_c[2];
    float c10 = g_c[3], c11 = g_c[4],  c12 = g_c[5];
    float c20 = g_c[6], c21 = g_c[7],  c22 = g_c[8];
    float c30 = g_c[9], c31 = g_c[10], c32 = g_c[11];

    float m0 = -INFINITY, m1 = -INFINITY, m2 = -INFINITY, m3 = -INFINITY;
    for (int i = r0 + lane; i < r1; i += 32) {
        int s = g_csr_src[i];
        float4 at = g_csr_att[i];
        float l0 = g_ss[s * 4 + 0] + sd0 + at.x * c00 + at.y * c01 + at.z * c02;
        float l1 = g_ss[s * 4 + 1] + sd1 + at.x * c10 + at.y * c11 + at.z * c12;
        float l2 = g_ss[s * 4 + 2] + sd2 + at.x * c20 + at.y * c21 + at.z * c22;
        float l3 = g_ss[s * 4 + 3] + sd3 + at.x * c30 + at.y * c31 + at.z * c32;
        l0 = l0 > 0.f ? l0 : NEG_SLOPE * l0;
        l1 = l1 > 0.f ? l1 : NEG_SLOPE * l1;
        l2 = l2 > 0.f ? l2 : NEG_SLOPE * l2;
        l3 = l3 > 0.f ? l3 : NEG_SLOPE * l3;
        m0 = fmaxf(m0, l0); m1 = fmaxf(m1, l1);
        m2 = fmaxf(m2, l2); m3 = fmaxf(m3, l3);
    }
    #pragma unroll
    for (int o = 16; o > 0; o >>= 1) {
        m0 = fmaxf(m0, __shfl_xor_sync(0xFFFFFFFFu, m0, o));
        m1 = fmaxf(m1, __shfl_xor_sync(0xFFFFFFFFu, m1, o));
        m2 = fmaxf(m2, __shfl_xor_sync(0xFFFFFFFFu, m2, o));
        m3 = fmaxf(m3, __shfl_xor_sync(0xFFFFFFFFu, m3, o));
    }
    float mh  = h == 0 ? m0 : (h == 1 ? m1 : (h == 2 ? m2 : m3));
    float sdh = h == 0 ? sd0 : (h == 1 ? sd1 : (h == 2 ? sd2 : sd3));
    float ch0 = h == 0 ? c00 : (h == 1 ? c10 : (h == 2 ? c20 : c30));
    float ch1 = h == 0 ? c01 : (h == 1 ? c11 : (h == 2 ? c21 : c31));
    float ch2 = h == 0 ? c02 : (h == 1 ? c12 : (h == 2 ? c22 : c32));

    float4 a0 = make_float4(0.f, 0.f, 0.f, 0.f);
    float4 a1 = make_float4(0.f, 0.f, 0.f, 0.f);
    float den = 0.f;
    for (int i = r0; i < r1; i++) {
        int s = g_csr_src[i];
        float4 at = g_csr_att[i];
        float l = g_ss[s * 4 + h] + sdh + at.x * ch0 + at.y * ch1 + at.z * ch2;
        l = l > 0.f ? l : NEG_SLOPE * l;
        float w = expf(l - mh);
        den += w;
        const float* row = &g_hp[(long long)s * HIDDEN + lane * 8];
        float4 v0 = *(const float4*)row;
        float4 v1 = *(const float4*)(row + 4);
        a0.x += w * v0.x; a0.y += w * v0.y; a0.z += w * v0.z; a0.w += w * v0.w;
        a1.x += w * v1.x; a1.y += w * v1.y; a1.z += w * v1.z; a1.w += w * v1.w;
    }
    float inv = 1.f / fmaxf(den, 1e-16f);
    hv0.x = elu1(a0.x * inv + hv0.x); hv0.y = elu1(a0.y * inv + hv0.y);
    hv0.z = elu1(a0.z * inv + hv0.z); hv0.w = elu1(a0.w * inv + hv0.w);
    hv1.x = elu1(a1.x * inv + hv1.x); hv1.y = elu1(a1.y * inv + hv1.y);
    hv1.z = elu1(a1.z * inv + hv1.z); hv1.w = elu1(a1.w * inv + hv1.w);
    *(float4*)&g_h[hb] = hv0;
    *(float4*)&g_h[hb + 4] = hv1;
}

// ---------------- output LN + ELU + write node_emb + pool ----------------
__global__ void ln_out_kernel(const float* __restrict__ lg,
                              const float* __restrict__ lb,
                              const int* __restrict__ batch,
                              float* __restrict__ node_out) {
    int n = blockIdx.x;
    int j = threadIdx.x;
    __shared__ float ws[8];
    float y = g_hp[(long long)n * HIDDEN + j];
    float mu = block_sum_256(y, ws) * (1.f / HIDDEN);
    float d = y - mu;
    float var = block_sum_256(d * d, ws) * (1.f / HIDDEN);
    float v = elu1(d * rsqrtf(var + 1e-5f) * lg[j] + lb[j]);
    node_out[(long long)n * HIDDEN + j] = v;
    int b = batch[n];
    atomicAdd(&g_pool[b * HIDDEN + j], v);
    if (j == 0) atomicAdd(&g_cnt[b], 1.0f);
}

// ---------------- graph mean pool output ----------------
__global__ void graph_out_kernel(float* __restrict__ out) {
    int i = blockIdx.x * blockDim.x + threadIdx.x;
    if (i < NUM_GRAPHS * HIDDEN) out[i] = g_pool[i] / fmaxf(g_cnt[i >> 8], 1.0f);
}

// ---------------- launch ----------------
extern "C" void kernel_launch(void* const* d_in, const int* in_sizes, int n_in,
                              void* d_out, int out_size) {
    const float* x          = (const float*)d_in[0];
    const int*   edge_index = (const int*)d_in[1];
    const float* edge_attr  = (const float*)d_in[2];
    const int*   batch      = (const int*)d_in[3];
    const float* W_in       = (const float*)d_in[4];
    const float* b_in       = (const float*)d_in[5];
    const float* ln_in_g    = (const float*)d_in[6];
    const float* ln_in_b    = (const float*)d_in[7];
    const float* W_gat      = (const float*)d_in[8];
    const float* b_gat      = (const float*)d_in[9];
    const float* W_e        = (const float*)d_in[10];
    const float* a_src      = (const float*)d_in[11];
    const float* a_dst      = (const float*)d_in[12];
    const float* a_edge     = (const float*)d_in[13];
    const float* W_out      = (const float*)d_in[14];
    const float* b_out      = (const float*)d_in[15];
    const float* ln_out_g   = (const float*)d_in[16];
    const float* ln_out_b   = (const float*)d_in[17];

    float* out = (float*)d_out;

    float *hp_, *h_;
    cudaGetSymbolAddress((void**)&h_, g_h);
    cudaGetSymbolAddress((void**)&hp_, g_hp);

    long long node_off = (long long)out_size - (long long)N_NODES * HIDDEN;
    float* node_out = (node_off >= 0) ? out + node_off : hp_;

    init_kernel<<<(N_NODES + 255) / 256, 256>>>();
    input_proj_kernel<<<N_NODES, HIDDEN>>>(x, W_in, b_in, ln_in_g, ln_in_b);
    hist_kernel<<<(N_EDGES + 255) / 256, 256>>>(edge_index);
    scan_fast_kernel<<<1, 1024>>>();
    scatter_kernel<<<(N_EDGES + 255) / 256, 256>>>(edge_index, edge_attr);

    dim3 gemm_grid(2, (N_NODES + GBM - 1) / GBM);
    int score_blocks = (N_NODES * HEADS * 32 + 255) / 256;
    int gat_blocks = (N_NODES * 32 + 255) / 256;

    for (int l = 0; l < LAYERS; l++) {
        const float* Wl  = W_gat + (long long)l * HIDDEN * HIDDEN;
        const float* bl  = b_gat + l * HIDDEN;
        const float* Wel = W_e + l * 3 * HIDDEN;
        const float* asl = a_src + l * HEADS * HEAD_DIM;
        const float* adl = a_dst + l * HEADS * HEAD_DIM;
        const float* ael = a_edge + l * HEADS * HEAD_DIM;

        gemm_mma_kernel<<<gemm_grid, 256>>>(h_, Wl, bl, hp_, N_NODES);
        node_score_kernel<<<score_blocks, 256>>>(asl, adl, Wel, ael);
        gat_fused_kernel<<<gat_blocks, 256>>>();
    }

    gemm_mma_kernel<<<gemm_grid, 256>>>(h_, W_out, b_out, hp_, N_NODES);
    ln_out_kernel<<<N_NODES, HIDDEN>>>(ln_out_g, ln_out_b, batch, node_out);
    graph_out_kernel<<<(NUM_GRAPHS * HIDDEN + 255) / 256, 256>>>(out);
}

// round 9
// speedup vs baseline: 3.2770x; 1.0800x over previous
#include <cuda_runtime.h>
#include <cuda_bf16.h>
#include <math.h>
#include <stdint.h>

#define N_NODES 50000
#define N_EDGES 800000
#define HIDDEN  256
#define HEADS   4
#define HEAD_DIM 64
#define LAYERS  3
#define NUM_GRAPHS 64
#define NEG_SLOPE 0.2f
#define SCAN_BLOCKS ((N_NODES + 1023) / 1024)   // 49

// ---------------- scratch (device globals; no allocation allowed) ----------------
__device__ float g_h   [(long long)N_NODES * HIDDEN];
__device__ float g_hp  [(long long)N_NODES * HIDDEN];
__device__ float g_ss  [N_NODES * HEADS];
__device__ float g_sd  [N_NODES * HEADS];
__device__ float g_c   [HEADS * 3];
__device__ float g_pool[NUM_GRAPHS * HIDDEN];
__device__ float g_cnt [NUM_GRAPHS];
// CSR scratch
__device__ int    g_deg[N_NODES];
__device__ int    g_off[N_NODES + 1];
__device__ int    g_cur[N_NODES];
__device__ int    g_bsum[SCAN_BLOCKS];
__device__ int    g_bsum_ex[SCAN_BLOCKS];
__device__ int    g_csr_src[N_EDGES];
__device__ float4 g_csr_att[N_EDGES];

// ---------------- helpers ----------------
__device__ __forceinline__ float elu1(float v) {
    return v > 0.f ? v : expm1f(v);
}

__device__ __forceinline__ uint32_t f2tf32(float x) {
    uint32_t u;
    asm("cvt.rna.tf32.f32 %0, %1;" : "=r"(u) : "f"(x));
    return u;
}

// ---------------- init: pooling accumulators + degree histogram ----------------
__global__ void init_kernel() {
    int i = blockIdx.x * blockDim.x + threadIdx.x;
    if (i < NUM_GRAPHS * HIDDEN) g_pool[i] = 0.f;
    if (i < NUM_GRAPHS) g_cnt[i] = 0.f;
    if (i < N_NODES) g_deg[i] = 0;
}

// ---------------- block LN reduce helper (256 threads) ----------------
__device__ __forceinline__ float block_sum_256(float v, float* ws) {
    int lane = threadIdx.x & 31, wid = threadIdx.x >> 5;
    #pragma unroll
    for (int o = 16; o > 0; o >>= 1) v += __shfl_xor_sync(0xFFFFFFFFu, v, o);
    if (lane == 0) ws[wid] = v;
    __syncthreads();
    float s = ws[0] + ws[1] + ws[2] + ws[3] + ws[4] + ws[5] + ws[6] + ws[7];
    __syncthreads();
    return s;
}

// ---------------- input projection + LN + ELU ----------------
__global__ void input_proj_kernel(const float* __restrict__ x,
                                  const float* __restrict__ Win,
                                  const float* __restrict__ bin,
                                  const float* __restrict__ lg,
                                  const float* __restrict__ lb) {
    int n = blockIdx.x;
    int j = threadIdx.x;
    __shared__ float xs[8];
    __shared__ float ws[8];
    if (j < 8) xs[j] = x[n * 8 + j];
    __syncthreads();
    float y = bin[j];
    #pragma unroll
    for (int k = 0; k < 8; k++) y += xs[k] * Win[k * HIDDEN + j];
    float mu = block_sum_256(y, ws) * (1.f / HIDDEN);
    float d = y - mu;
    float var = block_sum_256(d * d, ws) * (1.f / HIDDEN);
    float v = d * rsqrtf(var + 1e-5f) * lg[j] + lb[j];
    g_h[(long long)n * HIDDEN + j] = elu1(v);
}

// ---------------- CSR build ----------------
__global__ void hist_kernel(const int* __restrict__ ei) {
    int e = blockIdx.x * blockDim.x + threadIdx.x;
    if (e >= N_EDGES) return;
    atomicAdd(&g_deg[ei[N_EDGES + e]], 1);
}

// phase 1: per-block (1024-elem chunk) totals
__global__ void scan_reduce_kernel() {
    __shared__ int ws[8];
    int b = blockIdx.x;
    int t = threadIdx.x;             // 256 threads
    int base = b * 1024;
    int s = 0;
    #pragma unroll
    for (int i = 0; i < 4; i++) {
        int idx = base + t + i * 256;
        if (idx < N_NODES) s += g_deg[idx];
    }
    int lane = t & 31, wid = t >> 5;
    #pragma unroll
    for (int o = 16; o > 0; o >>= 1) s += __shfl_xor_sync(0xFFFFFFFFu, s, o);
    if (lane == 0) ws[wid] = s;
    __syncthreads();
    if (t == 0) g_bsum[b] = ws[0] + ws[1] + ws[2] + ws[3] + ws[4] + ws[5] + ws[6] + ws[7];
}

// phase 2: exclusive scan of 49 block sums (one 64-thread block)
__global__ void scan_tops_kernel() {
    __shared__ int w0tot;
    int t = threadIdx.x;             // 64 threads
    int lane = t & 31, wid = t >> 5;
    int v = (t < SCAN_BLOCKS) ? g_bsum[t] : 0;
    int incl = v;
    #pragma unroll
    for (int o = 1; o < 32; o <<= 1) {
        int y = __shfl_up_sync(0xFFFFFFFFu, incl, o);
        if (lane >= o) incl += y;
    }
    if (wid == 0 && lane == 31) w0tot = incl;
    __syncthreads();
    int ex = incl - v + (wid == 1 ? w0tot : 0);
    if (t < SCAN_BLOCKS) g_bsum_ex[t] = ex;
    if (t == 0) g_off[N_NODES] = N_EDGES;
}

// phase 3: block-local exclusive scan + add block offset
__global__ void scan_final_kernel() {
    __shared__ int wtot[32];
    int b = blockIdx.x;
    int t = threadIdx.x;             // 1024 threads
    int i = b * 1024 + t;
    int v = (i < N_NODES) ? g_deg[i] : 0;
    int lane = t & 31, wid = t >> 5;
    int incl = v;
    #pragma unroll
    for (int o = 1; o < 32; o <<= 1) {
        int y = __shfl_up_sync(0xFFFFFFFFu, incl, o);
        if (lane >= o) incl += y;
    }
    if (lane == 31) wtot[wid] = incl;
    __syncthreads();
    if (wid == 0) {
        int w = wtot[lane];
        #pragma unroll
        for (int o = 1; o < 32; o <<= 1) {
            int y = __shfl_up_sync(0xFFFFFFFFu, w, o);
            if (lane >= o) w += y;
        }
        wtot[lane] = w;
    }
    __syncthreads();
    int ex = incl - v + (wid > 0 ? wtot[wid - 1] : 0) + g_bsum_ex[b];
    if (i < N_NODES) {
        g_off[i] = ex;
        g_cur[i] = ex;
    }
}

__global__ void scatter_kernel(const int* __restrict__ ei,
                               const float* __restrict__ ea) {
    int e = blockIdx.x * blockDim.x + threadIdx.x;
    if (e >= N_EDGES) return;
    int s = ei[e];
    int d = ei[N_EDGES + e];
    int pos = atomicAdd(&g_cur[d], 1);
    g_csr_src[pos] = s;
    g_csr_att[pos] = make_float4(ea[e * 3 + 0], ea[e * 3 + 1], ea[e * 3 + 2], 0.f);
}

// ---------------- mma.sync tf32 GEMM: C[M,256] = A[M,256] @ B[256,256] + bias ----------------
// CTA 128x128, 8 warps (2M x 4N), warp tile 64x32 = 4x4 m16n8k8 fragments.
// Double-buffered smem mainloop; next chunk LDGs issued before current mma block.
#define GBM 128
#define GBN 128
#define GBK 32
#define A_STRIDE 36
#define B_STRIDE 136
#define ASZ (GBM * A_STRIDE)
#define BSZ (GBK * B_STRIDE)
#define GEMM_DSMEM (2 * (ASZ + BSZ) * 4)

__global__ void __launch_bounds__(256, 2)
gemm_mma_kernel(const float* __restrict__ A,
                const float* __restrict__ B,
                const float* __restrict__ bias,
                float* __restrict__ C,
                int M) {
    extern __shared__ uint32_t sm[];
    uint32_t* As = sm;               // [2][ASZ]
    uint32_t* Bs = sm + 2 * ASZ;     // [2][BSZ]

    int tid = threadIdx.x;
    int warp = tid >> 5;
    int lane = tid & 31;
    int wm = warp >> 2;
    int wn = warp & 3;
    int cCol = blockIdx.x;
    int cRow = blockIdx.y;

    // A loader: iteration i covers row arow_base + i*32, fixed k-group acol4
    int arow_base = tid >> 3;            // 0..31
    int acol4 = (tid & 7) * 4;           // 0..28
    // B loader: iteration i covers k row bk + i*8, fixed n-group bn4
    int bk = tid >> 5;                   // 0..7
    int bn4 = (tid & 31) * 4;            // 0..124
    const float* Bb = B + cCol * GBN;

    float acc[4][4][4];
    #pragma unroll
    for (int i = 0; i < 4; i++)
        #pragma unroll
        for (int j = 0; j < 4; j++)
            #pragma unroll
            for (int r = 0; r < 4; r++) acc[i][j][r] = 0.f;

    int lr = lane >> 2;
    int lc = lane & 3;

    float4 ar[4], br[4];
    // prologue: chunk 0
    #pragma unroll
    for (int i = 0; i < 4; i++) {
        int grow = cRow * GBM + arow_base + i * 32;
        ar[i] = (grow < M) ? *(const float4*)&A[(long long)grow * 256 + acol4]
                           : make_float4(0.f, 0.f, 0.f, 0.f);
        br[i] = *(const float4*)&Bb[(long long)(bk + i * 8) * 256 + bn4];
    }
    #pragma unroll
    for (int i = 0; i < 4; i++) {
        *(uint4*)&As[(arow_base + i * 32) * A_STRIDE + acol4] =
            make_uint4(f2tf32(ar[i].x), f2tf32(ar[i].y), f2tf32(ar[i].z), f2tf32(ar[i].w));
        *(uint4*)&Bs[(bk + i * 8) * B_STRIDE + bn4] =
            make_uint4(f2tf32(br[i].x), f2tf32(br[i].y), f2tf32(br[i].z), f2tf32(br[i].w));
    }
    __syncthreads();

    for (int kc = 0; kc < 256 / GBK; kc++) {
        int st = kc & 1;
        int nst = st ^ 1;
        // issue next-chunk LDGs before compute
        if (kc < 7) {
            int kb = (kc + 1) * GBK;
            #pragma unroll
            for (int i = 0; i < 4; i++) {
                int grow = cRow * GBM + arow_base + i * 32;
                ar[i] = (grow < M) ? *(const float4*)&A[(long long)grow * 256 + kb + acol4]
                                   : make_float4(0.f, 0.f, 0.f, 0.f);
                br[i] = *(const float4*)&Bb[(long long)(kb + bk + i * 8) * 256 + bn4];
            }
        }

        const uint32_t* Asb = As + st * ASZ;
        const uint32_t* Bsb = Bs + st * BSZ;
        #pragma unroll
        for (int ks = 0; ks < GBK / 8; ks++) {
            int k0 = ks * 8;
            uint32_t bf[4][2];
            #pragma unroll
            for (int nt = 0; nt < 4; nt++) {
                int nb = wn * 32 + nt * 8 + lr;
                bf[nt][0] = Bsb[(k0 + lc) * B_STRIDE + nb];
                bf[nt][1] = Bsb[(k0 + lc + 4) * B_STRIDE + nb];
            }
            #pragma unroll
            for (int mt = 0; mt < 4; mt++) {
                int rm = wm * 64 + mt * 16;
                uint32_t a0 = Asb[(rm + lr) * A_STRIDE + k0 + lc];
                uint32_t a1 = Asb[(rm + lr + 8) * A_STRIDE + k0 + lc];
                uint32_t a2 = Asb[(rm + lr) * A_STRIDE + k0 + lc + 4];
                uint32_t a3 = Asb[(rm + lr + 8) * A_STRIDE + k0 + lc + 4];
                #pragma unroll
                for (int nt = 0; nt < 4; nt++) {
                    asm volatile(
                        "mma.sync.aligned.m16n8k8.row.col.f32.tf32.tf32.f32 "
                        "{%0,%1,%2,%3}, {%4,%5,%6,%7}, {%8,%9}, {%0,%1,%2,%3};"
                        : "+f"(acc[mt][nt][0]), "+f"(acc[mt][nt][1]),
                          "+f"(acc[mt][nt][2]), "+f"(acc[mt][nt][3])
                        : "r"(a0), "r"(a1), "r"(a2), "r"(a3),
                          "r"(bf[nt][0]), "r"(bf[nt][1]));
                }
            }
        }
        if (kc < 7) {
            uint32_t* Asn = As + nst * ASZ;
            uint32_t* Bsn = Bs + nst * BSZ;
            #pragma unroll
            for (int i = 0; i < 4; i++) {
                *(uint4*)&Asn[(arow_base + i * 32) * A_STRIDE + acol4] =
                    make_uint4(f2tf32(ar[i].x), f2tf32(ar[i].y), f2tf32(ar[i].z), f2tf32(ar[i].w));
                *(uint4*)&Bsn[(bk + i * 8) * B_STRIDE + bn4] =
                    make_uint4(f2tf32(br[i].x), f2tf32(br[i].y), f2tf32(br[i].z), f2tf32(br[i].w));
            }
        }
        __syncthreads();
    }

    // epilogue: direct stores (+bias)
    #pragma unroll
    for (int mt = 0; mt < 4; mt++) {
        int row0 = cRow * GBM + wm * 64 + mt * 16 + lr;
        #pragma unroll
        for (int nt = 0; nt < 4; nt++) {
            int col = cCol * GBN + wn * 32 + nt * 8 + lc * 2;
            float b0 = bias[col], b1 = bias[col + 1];
            if (row0 < M) {
                float2 v0 = make_float2(acc[mt][nt][0] + b0, acc[mt][nt][1] + b1);
                *(float2*)&C[(long long)row0 * 256 + col] = v0;
            }
            if (row0 + 8 < M) {
                float2 v1 = make_float2(acc[mt][nt][2] + b0, acc[mt][nt][3] + b1);
                *(float2*)&C[(long long)(row0 + 8) * 256 + col] = v1;
            }
        }
    }
}

// ---------------- node attention scores (+ per-layer c precompute in block 0) ----------------
__global__ void node_score_kernel(const float* __restrict__ as_,
                                  const float* __restrict__ ad_,
                                  const float* __restrict__ We,
                                  const float* __restrict__ ae) {
    if (blockIdx.x == 0 && threadIdx.x < HEADS * 3) {
        int i = threadIdx.x;
        int hh = i / 3, k = i % 3;
        float s = 0.f;
        for (int d = 0; d < HEAD_DIM; d++)
            s += We[k * HIDDEN + hh * HEAD_DIM + d] * ae[hh * HEAD_DIM + d];
        g_c[i] = s;
    }
    int gw = (blockIdx.x * blockDim.x + threadIdx.x) >> 5;
    int lane = threadIdx.x & 31;
    if (gw >= N_NODES * HEADS) return;
    int n = gw >> 2, hh = gw & 3;
    const float* row = g_hp + (long long)n * HIDDEN + hh * HEAD_DIM;
    float v0 = row[lane], v1 = row[lane + 32];
    float s = v0 * as_[hh * HEAD_DIM + lane] + v1 * as_[hh * HEAD_DIM + lane + 32];
    float t = v0 * ad_[hh * HEAD_DIM + lane] + v1 * ad_[hh * HEAD_DIM + lane + 32];
    #pragma unroll
    for (int o = 16; o > 0; o >>= 1) {
        s += __shfl_xor_sync(0xFFFFFFFFu, s, o);
        t += __shfl_xor_sync(0xFFFFFFFFu, t, o);
    }
    if (lane == 0) {
        g_ss[gw] = s;
        g_sd[gw] = t;
    }
}

// ---------------- fused GAT layer: softmax + message agg + residual + ELU ----------------
__global__ void gat_fused_kernel() {
    int gw = (blockIdx.x * blockDim.x + threadIdx.x) >> 5;
    int lane = threadIdx.x & 31;
    if (gw >= N_NODES) return;
    int n = gw;
    int r0 = g_off[n], r1 = g_off[n + 1];
    int h = lane >> 3;
    long long hb = (long long)n * HIDDEN + lane * 8;
    float4 hv0 = *(const float4*)&g_h[hb];
    float4 hv1 = *(const float4*)&g_h[hb + 4];

    if (r0 == r1) {
        hv0.x = elu1(hv0.x); hv0.y = elu1(hv0.y); hv0.z = elu1(hv0.z); hv0.w = elu1(hv0.w);
        hv1.x = elu1(hv1.x); hv1.y = elu1(hv1.y); hv1.z = elu1(hv1.z); hv1.w = elu1(hv1.w);
        *(float4*)&g_h[hb] = hv0;
        *(float4*)&g_h[hb + 4] = hv1;
        return;
    }

    float sd0 = g_sd[n * 4 + 0], sd1 = g_sd[n * 4 + 1];
    float sd2 = g_sd[n * 4 + 2], sd3 = g_sd[n * 4 + 3];
    float c00 = g_c[0], c01 = g_c[1],  c02 = g_c[2];
    float c10 = g_c[3], c11 = g_c[4],  c12 = g_c[5];
    float c20 = g_c[6], c21 = g_c[7],  c22 = g_c[8];
    float c30 = g_c[9], c31 = g_c[10], c32 = g_c[11];

    float m0 = -INFINITY, m1 = -INFINITY, m2 = -INFINITY, m3 = -INFINITY;
    for (int i = r0 + lane; i < r1; i += 32) {
        int s = g_csr_src[i];
        float4 at = g_csr_att[i];
        float l0 = g_ss[s * 4 + 0] + sd0 + at.x * c00 + at.y * c01 + at.z * c02;
        float l1 = g_ss[s * 4 + 1] + sd1 + at.x * c10 + at.y * c11 + at.z * c12;
        float l2 = g_ss[s * 4 + 2] + sd2 + at.x * c20 + at.y * c21 + at.z * c22;
        float l3 = g_ss[s * 4 + 3] + sd3 + at.x * c30 + at.y * c31 + at.z * c32;
        l0 = l0 > 0.f ? l0 : NEG_SLOPE * l0;
        l1 = l1 > 0.f ? l1 : NEG_SLOPE * l1;
        l2 = l2 > 0.f ? l2 : NEG_SLOPE * l2;
        l3 = l3 > 0.f ? l3 : NEG_SLOPE * l3;
        m0 = fmaxf(m0, l0); m1 = fmaxf(m1, l1);
        m2 = fmaxf(m2, l2); m3 = fmaxf(m3, l3);
    }
    #pragma unroll
    for (int o = 16; o > 0; o >>= 1) {
        m0 = fmaxf(m0, __shfl_xor_sync(0xFFFFFFFFu, m0, o));
        m1 = fmaxf(m1, __shfl_xor_sync(0xFFFFFFFFu, m1, o));
        m2 = fmaxf(m2, __shfl_xor_sync(0xFFFFFFFFu, m2, o));
        m3 = fmaxf(m3, __shfl_xor_sync(0xFFFFFFFFu, m3, o));
    }
    float mh  = h == 0 ? m0 : (h == 1 ? m1 : (h == 2 ? m2 : m3));
    float sdh = h == 0 ? sd0 : (h == 1 ? sd1 : (h == 2 ? sd2 : sd3));
    float ch0 = h == 0 ? c00 : (h == 1 ? c10 : (h == 2 ? c20 : c30));
    float ch1 = h == 0 ? c01 : (h == 1 ? c11 : (h == 2 ? c21 : c31));
    float ch2 = h == 0 ? c02 : (h == 1 ? c12 : (h == 2 ? c22 : c32));

    float4 a0 = make_float4(0.f, 0.f, 0.f, 0.f);
    float4 a1 = make_float4(0.f, 0.f, 0.f, 0.f);
    float den = 0.f;
    for (int i = r0; i < r1; i++) {
        int s = g_csr_src[i];
        float4 at = g_csr_att[i];
        float l = g_ss[s * 4 + h] + sdh + at.x * ch0 + at.y * ch1 + at.z * ch2;
        l = l > 0.f ? l : NEG_SLOPE * l;
        float w = expf(l - mh);
        den += w;
        const float* row = &g_hp[(long long)s * HIDDEN + lane * 8];
        float4 v0 = *(const float4*)row;
        float4 v1 = *(const float4*)(row + 4);
        a0.x += w * v0.x; a0.y += w * v0.y; a0.z += w * v0.z; a0.w += w * v0.w;
        a1.x += w * v1.x; a1.y += w * v1.y; a1.z += w * v1.z; a1.w += w * v1.w;
    }
    float inv = 1.f / fmaxf(den, 1e-16f);
    hv0.x = elu1(a0.x * inv + hv0.x); hv0.y = elu1(a0.y * inv + hv0.y);
    hv0.z = elu1(a0.z * inv + hv0.z); hv0.w = elu1(a0.w * inv + hv0.w);
    hv1.x = elu1(a1.x * inv + hv1.x); hv1.y = elu1(a1.y * inv + hv1.y);
    hv1.z = elu1(a1.z * inv + hv1.z); hv1.w = elu1(a1.w * inv + hv1.w);
    *(float4*)&g_h[hb] = hv0;
    *(float4*)&g_h[hb + 4] = hv1;
}

// ---------------- output LN + ELU + write node_emb + pool ----------------
__global__ void ln_out_kernel(const float* __restrict__ lg,
                              const float* __restrict__ lb,
                              const int* __restrict__ batch,
                              float* __restrict__ node_out) {
    int n = blockIdx.x;
    int j = threadIdx.x;
    __shared__ float ws[8];
    float y = g_hp[(long long)n * HIDDEN + j];
    float mu = block_sum_256(y, ws) * (1.f / HIDDEN);
    float d = y - mu;
    float var = block_sum_256(d * d, ws) * (1.f / HIDDEN);
    float v = elu1(d * rsqrtf(var + 1e-5f) * lg[j] + lb[j]);
    node_out[(long long)n * HIDDEN + j] = v;
    int b = batch[n];
    atomicAdd(&g_pool[b * HIDDEN + j], v);
    if (j == 0) atomicAdd(&g_cnt[b], 1.0f);
}

// ---------------- graph mean pool output ----------------
__global__ void graph_out_kernel(float* __restrict__ out) {
    int i = blockIdx.x * blockDim.x + threadIdx.x;
    if (i < NUM_GRAPHS * HIDDEN) out[i] = g_pool[i] / fmaxf(g_cnt[i >> 8], 1.0f);
}

// ---------------- launch ----------------
extern "C" void kernel_launch(void* const* d_in, const int* in_sizes, int n_in,
                              void* d_out, int out_size) {
    const float* x          = (const float*)d_in[0];
    const int*   edge_index = (const int*)d_in[1];
    const float* edge_attr  = (const float*)d_in[2];
    const int*   batch      = (const int*)d_in[3];
    const float* W_in       = (const float*)d_in[4];
    const float* b_in       = (const float*)d_in[5];
    const float* ln_in_g    = (const float*)d_in[6];
    const float* ln_in_b    = (const float*)d_in[7];
    const float* W_gat      = (const float*)d_in[8];
    const float* b_gat      = (const float*)d_in[9];
    const float* W_e        = (const float*)d_in[10];
    const float* a_src      = (const float*)d_in[11];
    const float* a_dst      = (const float*)d_in[12];
    const float* a_edge     = (const float*)d_in[13];
    const float* W_out      = (const float*)d_in[14];
    const float* b_out      = (const float*)d_in[15];
    const float* ln_out_g   = (const float*)d_in[16];
    const float* ln_out_b   = (const float*)d_in[17];

    float* out = (float*)d_out;

    float *hp_, *h_;
    cudaGetSymbolAddress((void**)&h_, g_h);
    cudaGetSymbolAddress((void**)&hp_, g_hp);

    long long node_off = (long long)out_size - (long long)N_NODES * HIDDEN;
    float* node_out = (node_off >= 0) ? out + node_off : hp_;

    static int smem_set = 0;
    if (!smem_set) {
        cudaFuncSetAttribute(gemm_mma_kernel, cudaFuncAttributeMaxDynamicSharedMemorySize,
                             GEMM_DSMEM);
        smem_set = 1;
    }

    init_kernel<<<(N_NODES + 255) / 256, 256>>>();
    input_proj_kernel<<<N_NODES, HIDDEN>>>(x, W_in, b_in, ln_in_g, ln_in_b);
    hist_kernel<<<(N_EDGES + 255) / 256, 256>>>(edge_index);
    scan_reduce_kernel<<<SCAN_BLOCKS, 256>>>();
    scan_tops_kernel<<<1, 64>>>();
    scan_final_kernel<<<SCAN_BLOCKS, 1024>>>();
    scatter_kernel<<<(N_EDGES + 255) / 256, 256>>>(edge_index, edge_attr);

    dim3 gemm_grid(2, (N_NODES + GBM - 1) / GBM);
    int score_blocks = (N_NODES * HEADS * 32 + 255) / 256;
    int gat_blocks = (N_NODES * 32 + 255) / 256;

    for (int l = 0; l < LAYERS; l++) {
        const float* Wl  = W_gat + (long long)l * HIDDEN * HIDDEN;
        const float* bl  = b_gat + l * HIDDEN;
        const float* Wel = W_e + l * 3 * HIDDEN;
        const float* asl = a_src + l * HEADS * HEAD_DIM;
        const float* adl = a_dst + l * HEADS * HEAD_DIM;
        const float* ael = a_edge + l * HEADS * HEAD_DIM;

        gemm_mma_kernel<<<gemm_grid, 256, GEMM_DSMEM>>>(h_, Wl, bl, hp_, N_NODES);
        node_score_kernel<<<score_blocks, 256>>>(asl, adl, Wel, ael);
        gat_fused_kernel<<<gat_blocks, 256>>>();
    }

    gemm_mma_kernel<<<gemm_grid, 256, GEMM_DSMEM>>>(h_, W_out, b_out, hp_, N_NODES);
    ln_out_kernel<<<N_NODES, HIDDEN>>>(ln_out_g, ln_out_b, batch, node_out);
    graph_out_kernel<<<(NUM_GRAPHS * HIDDEN + 255) / 256, 256>>>(out);
}

// round 10
// speedup vs baseline: 3.7126x; 1.1329x over previous
#include <cuda_runtime.h>
#include <cuda_bf16.h>
#include <cuda_fp16.h>
#include <math.h>
#include <stdint.h>

#define N_NODES 50000
#define N_EDGES 800000
#define HIDDEN  256
#define HEADS   4
#define HEAD_DIM 64
#define LAYERS  3
#define NUM_GRAPHS 64
#define NEG_SLOPE 0.2f
#define SCAN_BLOCKS ((N_NODES + 1023) / 1024)   // 49

// ---------------- scratch (device globals; no allocation allowed) ----------------
__device__ float  g_h   [(long long)N_NODES * HIDDEN];
__device__ float  g_hp  [(long long)N_NODES * HIDDEN];
__device__ __half g_hph [(long long)N_NODES * HIDDEN];   // fp16 copy of g_hp for gather
__device__ float  g_ss  [N_NODES * HEADS];
__device__ float  g_sd  [N_NODES * HEADS];
__device__ float  g_c   [HEADS * 3];
__device__ float  g_pool[NUM_GRAPHS * HIDDEN];
__device__ float  g_cnt [NUM_GRAPHS];
// CSR scratch
__device__ int    g_deg[N_NODES];
__device__ int    g_off[N_NODES + 1];
__device__ int    g_cur[N_NODES];
__device__ int    g_bsum[SCAN_BLOCKS];
__device__ int    g_csr_src[N_EDGES];
__device__ float4 g_csr_att[N_EDGES];
__device__ float4 g_elog[N_EDGES];                       // per-layer leaky logits (4 heads)

// ---------------- helpers ----------------
__device__ __forceinline__ float elu1(float v) {
    return v > 0.f ? v : expm1f(v);
}

__device__ __forceinline__ uint32_t f2tf32(float x) {
    uint32_t u;
    asm("cvt.rna.tf32.f32 %0, %1;" : "=r"(u) : "f"(x));
    return u;
}

// ---------------- init: pooling accumulators + degree histogram ----------------
__global__ void init_kernel() {
    int i = blockIdx.x * blockDim.x + threadIdx.x;
    if (i < NUM_GRAPHS * HIDDEN) g_pool[i] = 0.f;
    if (i < NUM_GRAPHS) g_cnt[i] = 0.f;
    if (i < N_NODES) g_deg[i] = 0;
}

// ---------------- block LN reduce helper (256 threads) ----------------
__device__ __forceinline__ float block_sum_256(float v, float* ws) {
    int lane = threadIdx.x & 31, wid = threadIdx.x >> 5;
    #pragma unroll
    for (int o = 16; o > 0; o >>= 1) v += __shfl_xor_sync(0xFFFFFFFFu, v, o);
    if (lane == 0) ws[wid] = v;
    __syncthreads();
    float s = ws[0] + ws[1] + ws[2] + ws[3] + ws[4] + ws[5] + ws[6] + ws[7];
    __syncthreads();
    return s;
}

// ---------------- input projection + LN + ELU ----------------
__global__ void input_proj_kernel(const float* __restrict__ x,
                                  const float* __restrict__ Win,
                                  const float* __restrict__ bin,
                                  const float* __restrict__ lg,
                                  const float* __restrict__ lb) {
    int n = blockIdx.x;
    int j = threadIdx.x;
    __shared__ float xs[8];
    __shared__ float ws[8];
    if (j < 8) xs[j] = x[n * 8 + j];
    __syncthreads();
    float y = bin[j];
    #pragma unroll
    for (int k = 0; k < 8; k++) y += xs[k] * Win[k * HIDDEN + j];
    float mu = block_sum_256(y, ws) * (1.f / HIDDEN);
    float d = y - mu;
    float var = block_sum_256(d * d, ws) * (1.f / HIDDEN);
    float v = d * rsqrtf(var + 1e-5f) * lg[j] + lb[j];
    g_h[(long long)n * HIDDEN + j] = elu1(v);
}

// ---------------- CSR build ----------------
__global__ void hist_kernel(const int* __restrict__ ei) {
    int e = blockIdx.x * blockDim.x + threadIdx.x;
    if (e >= N_EDGES) return;
    atomicAdd(&g_deg[ei[N_EDGES + e]], 1);
}

// phase 1: per-block (1024-elem chunk) totals
__global__ void scan_reduce_kernel() {
    __shared__ int ws[8];
    int b = blockIdx.x;
    int t = threadIdx.x;             // 256 threads
    int base = b * 1024;
    int s = 0;
    #pragma unroll
    for (int i = 0; i < 4; i++) {
        int idx = base + t + i * 256;
        if (idx < N_NODES) s += g_deg[idx];
    }
    int lane = t & 31, wid = t >> 5;
    #pragma unroll
    for (int o = 16; o > 0; o >>= 1) s += __shfl_xor_sync(0xFFFFFFFFu, s, o);
    if (lane == 0) ws[wid] = s;
    __syncthreads();
    if (t == 0) g_bsum[b] = ws[0] + ws[1] + ws[2] + ws[3] + ws[4] + ws[5] + ws[6] + ws[7];
}

// phase 2: block-local exclusive scan + inline top-level scan of 49 block sums
__global__ void scan_final_kernel() {
    __shared__ int wtot[32];
    __shared__ int bex[SCAN_BLOCKS];
    int b = blockIdx.x;
    int t = threadIdx.x;             // 1024 threads
    int lane = t & 31, wid = t >> 5;

    // warp 0: exclusive-scan the 49 block sums into bex (redundant per block, trivial cost)
    if (wid == 0) {
        int v = (lane < SCAN_BLOCKS) ? g_bsum[lane] : 0;
        int incl = v;
        #pragma unroll
        for (int o = 1; o < 32; o <<= 1) {
            int y = __shfl_up_sync(0xFFFFFFFFu, incl, o);
            if (lane >= o) incl += y;
        }
        if (lane < SCAN_BLOCKS) bex[lane] = incl - v;
        int tot = __shfl_sync(0xFFFFFFFFu, incl, 31);
        int v2 = (lane + 32 < SCAN_BLOCKS) ? g_bsum[lane + 32] : 0;
        int incl2 = v2;
        #pragma unroll
        for (int o = 1; o < 32; o <<= 1) {
            int y = __shfl_up_sync(0xFFFFFFFFu, incl2, o);
            if (lane >= o) incl2 += y;
        }
        if (lane + 32 < SCAN_BLOCKS) bex[lane + 32] = tot + incl2 - v2;
    }

    int i = b * 1024 + t;
    int v = (i < N_NODES) ? g_deg[i] : 0;
    int incl = v;
    #pragma unroll
    for (int o = 1; o < 32; o <<= 1) {
        int y = __shfl_up_sync(0xFFFFFFFFu, incl, o);
        if (lane >= o) incl += y;
    }
    if (lane == 31) wtot[wid] = incl;
    __syncthreads();
    if (wid == 0) {
        int w = wtot[lane];
        #pragma unroll
        for (int o = 1; o < 32; o <<= 1) {
            int y = __shfl_up_sync(0xFFFFFFFFu, w, o);
            if (lane >= o) w += y;
        }
        wtot[lane] = w;
    }
    __syncthreads();
    int ex = incl - v + (wid > 0 ? wtot[wid - 1] : 0) + bex[b];
    if (i < N_NODES) {
        g_off[i] = ex;
        g_cur[i] = ex;
    }
    if (b == 0 && t == 0) g_off[N_NODES] = N_EDGES;
}

__global__ void scatter_kernel(const int* __restrict__ ei,
                               const float* __restrict__ ea) {
    int e = blockIdx.x * blockDim.x + threadIdx.x;
    if (e >= N_EDGES) return;
    int s = ei[e];
    int d = ei[N_EDGES + e];
    int pos = atomicAdd(&g_cur[d], 1);
    g_csr_src[pos] = s;
    g_csr_att[pos] = make_float4(ea[e * 3 + 0], ea[e * 3 + 1], ea[e * 3 + 2], 0.f);
}

// ---------------- mma.sync tf32 GEMM: C[M,256] = A[M,256] @ B[256,256] + bias ----------------
// CTA 128x128, 8 warps (2M x 4N), warp tile 64x32 = 4x4 m16n8k8 fragments.
// Double-buffered smem; epilogue writes f32 C and an fp16 copy for the GAT gather.
#define GBM 128
#define GBN 128
#define GBK 32
#define A_STRIDE 36
#define B_STRIDE 136
#define ASZ (GBM * A_STRIDE)
#define BSZ (GBK * B_STRIDE)
#define GEMM_DSMEM (2 * (ASZ + BSZ) * 4)

__global__ void __launch_bounds__(256, 2)
gemm_mma_kernel(const float* __restrict__ A,
                const float* __restrict__ B,
                const float* __restrict__ bias,
                float* __restrict__ C,
                int M) {
    extern __shared__ uint32_t sm[];
    uint32_t* As = sm;               // [2][ASZ]
    uint32_t* Bs = sm + 2 * ASZ;     // [2][BSZ]

    int tid = threadIdx.x;
    int warp = tid >> 5;
    int lane = tid & 31;
    int wm = warp >> 2;
    int wn = warp & 3;
    int cCol = blockIdx.x;
    int cRow = blockIdx.y;

    int arow_base = tid >> 3;            // 0..31
    int acol4 = (tid & 7) * 4;           // 0..28
    int bk = tid >> 5;                   // 0..7
    int bn4 = (tid & 31) * 4;            // 0..124
    const float* Bb = B + cCol * GBN;

    float acc[4][4][4];
    #pragma unroll
    for (int i = 0; i < 4; i++)
        #pragma unroll
        for (int j = 0; j < 4; j++)
            #pragma unroll
            for (int r = 0; r < 4; r++) acc[i][j][r] = 0.f;

    int lr = lane >> 2;
    int lc = lane & 3;

    float4 ar[4], br[4];
    #pragma unroll
    for (int i = 0; i < 4; i++) {
        int grow = cRow * GBM + arow_base + i * 32;
        ar[i] = (grow < M) ? *(const float4*)&A[(long long)grow * 256 + acol4]
                           : make_float4(0.f, 0.f, 0.f, 0.f);
        br[i] = *(const float4*)&Bb[(long long)(bk + i * 8) * 256 + bn4];
    }
    #pragma unroll
    for (int i = 0; i < 4; i++) {
        *(uint4*)&As[(arow_base + i * 32) * A_STRIDE + acol4] =
            make_uint4(f2tf32(ar[i].x), f2tf32(ar[i].y), f2tf32(ar[i].z), f2tf32(ar[i].w));
        *(uint4*)&Bs[(bk + i * 8) * B_STRIDE + bn4] =
            make_uint4(f2tf32(br[i].x), f2tf32(br[i].y), f2tf32(br[i].z), f2tf32(br[i].w));
    }
    __syncthreads();

    for (int kc = 0; kc < 256 / GBK; kc++) {
        int st = kc & 1;
        int nst = st ^ 1;
        if (kc < 7) {
            int kb = (kc + 1) * GBK;
            #pragma unroll
            for (int i = 0; i < 4; i++) {
                int grow = cRow * GBM + arow_base + i * 32;
                ar[i] = (grow < M) ? *(const float4*)&A[(long long)grow * 256 + kb + acol4]
                                   : make_float4(0.f, 0.f, 0.f, 0.f);
                br[i] = *(const float4*)&Bb[(long long)(kb + bk + i * 8) * 256 + bn4];
            }
        }

        const uint32_t* Asb = As + st * ASZ;
        const uint32_t* Bsb = Bs + st * BSZ;
        #pragma unroll
        for (int ks = 0; ks < GBK / 8; ks++) {
            int k0 = ks * 8;
            uint32_t bf[4][2];
            #pragma unroll
            for (int nt = 0; nt < 4; nt++) {
                int nb = wn * 32 + nt * 8 + lr;
                bf[nt][0] = Bsb[(k0 + lc) * B_STRIDE + nb];
                bf[nt][1] = Bsb[(k0 + lc + 4) * B_STRIDE + nb];
            }
            #pragma unroll
            for (int mt = 0; mt < 4; mt++) {
                int rm = wm * 64 + mt * 16;
                uint32_t a0 = Asb[(rm + lr) * A_STRIDE + k0 + lc];
                uint32_t a1 = Asb[(rm + lr + 8) * A_STRIDE + k0 + lc];
                uint32_t a2 = Asb[(rm + lr) * A_STRIDE + k0 + lc + 4];
                uint32_t a3 = Asb[(rm + lr + 8) * A_STRIDE + k0 + lc + 4];
                #pragma unroll
                for (int nt = 0; nt < 4; nt++) {
                    asm volatile(
                        "mma.sync.aligned.m16n8k8.row.col.f32.tf32.tf32.f32 "
                        "{%0,%1,%2,%3}, {%4,%5,%6,%7}, {%8,%9}, {%0,%1,%2,%3};"
                        : "+f"(acc[mt][nt][0]), "+f"(acc[mt][nt][1]),
                          "+f"(acc[mt][nt][2]), "+f"(acc[mt][nt][3])
                        : "r"(a0), "r"(a1), "r"(a2), "r"(a3),
                          "r"(bf[nt][0]), "r"(bf[nt][1]));
                }
            }
        }
        if (kc < 7) {
            uint32_t* Asn = As + nst * ASZ;
            uint32_t* Bsn = Bs + nst * BSZ;
            #pragma unroll
            for (int i = 0; i < 4; i++) {
                *(uint4*)&Asn[(arow_base + i * 32) * A_STRIDE + acol4] =
                    make_uint4(f2tf32(ar[i].x), f2tf32(ar[i].y), f2tf32(ar[i].z), f2tf32(ar[i].w));
                *(uint4*)&Bsn[(bk + i * 8) * B_STRIDE + bn4] =
                    make_uint4(f2tf32(br[i].x), f2tf32(br[i].y), f2tf32(br[i].z), f2tf32(br[i].w));
            }
        }
        __syncthreads();
    }

    // epilogue: f32 C (+bias) and fp16 copy for the gather path
    #pragma unroll
    for (int mt = 0; mt < 4; mt++) {
        int row0 = cRow * GBM + wm * 64 + mt * 16 + lr;
        #pragma unroll
        for (int nt = 0; nt < 4; nt++) {
            int col = cCol * GBN + wn * 32 + nt * 8 + lc * 2;
            float b0 = bias[col], b1 = bias[col + 1];
            if (row0 < M) {
                float2 v0 = make_float2(acc[mt][nt][0] + b0, acc[mt][nt][1] + b1);
                *(float2*)&C[(long long)row0 * 256 + col] = v0;
                *(__half2*)&g_hph[(long long)row0 * 256 + col] = __floats2half2_rn(v0.x, v0.y);
            }
            if (row0 + 8 < M) {
                float2 v1 = make_float2(acc[mt][nt][2] + b0, acc[mt][nt][3] + b1);
                *(float2*)&C[(long long)(row0 + 8) * 256 + col] = v1;
                *(__half2*)&g_hph[(long long)(row0 + 8) * 256 + col] = __floats2half2_rn(v1.x, v1.y);
            }
        }
    }
}

// ---------------- node attention scores (+ per-layer c precompute in block 0) ----------------
__global__ void node_score_kernel(const float* __restrict__ as_,
                                  const float* __restrict__ ad_,
                                  const float* __restrict__ We,
                                  const float* __restrict__ ae) {
    if (blockIdx.x == 0 && threadIdx.x < HEADS * 3) {
        int i = threadIdx.x;
        int hh = i / 3, k = i % 3;
        float s = 0.f;
        for (int d = 0; d < HEAD_DIM; d++)
            s += We[k * HIDDEN + hh * HEAD_DIM + d] * ae[hh * HEAD_DIM + d];
        g_c[i] = s;
    }
    int gw = (blockIdx.x * blockDim.x + threadIdx.x) >> 5;
    int lane = threadIdx.x & 31;
    if (gw >= N_NODES * HEADS) return;
    int n = gw >> 2, hh = gw & 3;
    const float* row = g_hp + (long long)n * HIDDEN + hh * HEAD_DIM;
    float v0 = row[lane], v1 = row[lane + 32];
    float s = v0 * as_[hh * HEAD_DIM + lane] + v1 * as_[hh * HEAD_DIM + lane + 32];
    float t = v0 * ad_[hh * HEAD_DIM + lane] + v1 * ad_[hh * HEAD_DIM + lane + 32];
    #pragma unroll
    for (int o = 16; o > 0; o >>= 1) {
        s += __shfl_xor_sync(0xFFFFFFFFu, s, o);
        t += __shfl_xor_sync(0xFFFFFFFFu, t, o);
    }
    if (lane == 0) {
        g_ss[gw] = s;
        g_sd[gw] = t;
    }
}

// ---------------- fused GAT layer: softmax + message agg + residual + ELU ----------------
// pass A stores leaky logits to g_elog; pass B gathers fp16 rows
__global__ void gat_fused_kernel() {
    int gw = (blockIdx.x * blockDim.x + threadIdx.x) >> 5;
    int lane = threadIdx.x & 31;
    if (gw >= N_NODES) return;
    int n = gw;
    int r0 = g_off[n], r1 = g_off[n + 1];
    int h = lane >> 3;
    long long hb = (long long)n * HIDDEN + lane * 8;
    float4 hv0 = *(const float4*)&g_h[hb];
    float4 hv1 = *(const float4*)&g_h[hb + 4];

    if (r0 == r1) {
        hv0.x = elu1(hv0.x); hv0.y = elu1(hv0.y); hv0.z = elu1(hv0.z); hv0.w = elu1(hv0.w);
        hv1.x = elu1(hv1.x); hv1.y = elu1(hv1.y); hv1.z = elu1(hv1.z); hv1.w = elu1(hv1.w);
        *(float4*)&g_h[hb] = hv0;
        *(float4*)&g_h[hb + 4] = hv1;
        return;
    }

    float sd0 = g_sd[n * 4 + 0], sd1 = g_sd[n * 4 + 1];
    float sd2 = g_sd[n * 4 + 2], sd3 = g_sd[n * 4 + 3];
    float c00 = g_c[0], c01 = g_c[1],  c02 = g_c[2];
    float c10 = g_c[3], c11 = g_c[4],  c12 = g_c[5];
    float c20 = g_c[6], c21 = g_c[7],  c22 = g_c[8];
    float c30 = g_c[9], c31 = g_c[10], c32 = g_c[11];

    // pass A: logits + per-head max; store leaky logits for pass B
    float m0 = -INFINITY, m1 = -INFINITY, m2 = -INFINITY, m3 = -INFINITY;
    for (int i = r0 + lane; i < r1; i += 32) {
        int s = g_csr_src[i];
        float4 at = g_csr_att[i];
        float l0 = g_ss[s * 4 + 0] + sd0 + at.x * c00 + at.y * c01 + at.z * c02;
        float l1 = g_ss[s * 4 + 1] + sd1 + at.x * c10 + at.y * c11 + at.z * c12;
        float l2 = g_ss[s * 4 + 2] + sd2 + at.x * c20 + at.y * c21 + at.z * c22;
        float l3 = g_ss[s * 4 + 3] + sd3 + at.x * c30 + at.y * c31 + at.z * c32;
        l0 = l0 > 0.f ? l0 : NEG_SLOPE * l0;
        l1 = l1 > 0.f ? l1 : NEG_SLOPE * l1;
        l2 = l2 > 0.f ? l2 : NEG_SLOPE * l2;
        l3 = l3 > 0.f ? l3 : NEG_SLOPE * l3;
        g_elog[i] = make_float4(l0, l1, l2, l3);
        m0 = fmaxf(m0, l0); m1 = fmaxf(m1, l1);
        m2 = fmaxf(m2, l2); m3 = fmaxf(m3, l3);
    }
    #pragma unroll
    for (int o = 16; o > 0; o >>= 1) {
        m0 = fmaxf(m0, __shfl_xor_sync(0xFFFFFFFFu, m0, o));
        m1 = fmaxf(m1, __shfl_xor_sync(0xFFFFFFFFu, m1, o));
        m2 = fmaxf(m2, __shfl_xor_sync(0xFFFFFFFFu, m2, o));
        m3 = fmaxf(m3, __shfl_xor_sync(0xFFFFFFFFu, m3, o));
    }
    float mh = h == 0 ? m0 : (h == 1 ? m1 : (h == 2 ? m2 : m3));
    __syncwarp();   // make lane-written g_elog visible warp-wide

    // pass B: denom + weighted fp16-row aggregation
    const float* elog = (const float*)g_elog;
    float4 a0 = make_float4(0.f, 0.f, 0.f, 0.f);
    float4 a1 = make_float4(0.f, 0.f, 0.f, 0.f);
    float den = 0.f;
    for (int i = r0; i < r1; i++) {
        int s = g_csr_src[i];
        float w = expf(elog[(long long)i * 4 + h] - mh);
        den += w;
        uint4 u = *(const uint4*)&g_hph[(long long)s * HIDDEN + lane * 8];
        float2 f0 = __half22float2(*(__half2*)&u.x);
        float2 f1 = __half22float2(*(__half2*)&u.y);
        float2 f2 = __half22float2(*(__half2*)&u.z);
        float2 f3 = __half22float2(*(__half2*)&u.w);
        a0.x += w * f0.x; a0.y += w * f0.y; a0.z += w * f1.x; a0.w += w * f1.y;
        a1.x += w * f2.x; a1.y += w * f2.y; a1.z += w * f3.x; a1.w += w * f3.y;
    }
    float inv = 1.f / fmaxf(den, 1e-16f);
    hv0.x = elu1(a0.x * inv + hv0.x); hv0.y = elu1(a0.y * inv + hv0.y);
    hv0.z = elu1(a0.z * inv + hv0.z); hv0.w = elu1(a0.w * inv + hv0.w);
    hv1.x = elu1(a1.x * inv + hv1.x); hv1.y = elu1(a1.y * inv + hv1.y);
    hv1.z = elu1(a1.z * inv + hv1.z); hv1.w = elu1(a1.w * inv + hv1.w);
    *(float4*)&g_h[hb] = hv0;
    *(float4*)&g_h[hb + 4] = hv1;
}

// ---------------- output LN + ELU + write node_emb + pool ----------------
__global__ void ln_out_kernel(const float* __restrict__ lg,
                              const float* __restrict__ lb,
                              const int* __restrict__ batch,
                              float* __restrict__ node_out) {
    int n = blockIdx.x;
    int j = threadIdx.x;
    __shared__ float ws[8];
    float y = g_hp[(long long)n * HIDDEN + j];
    float mu = block_sum_256(y, ws) * (1.f / HIDDEN);
    float d = y - mu;
    float var = block_sum_256(d * d, ws) * (1.f / HIDDEN);
    float v = elu1(d * rsqrtf(var + 1e-5f) * lg[j] + lb[j]);
    node_out[(long long)n * HIDDEN + j] = v;
    int b = batch[n];
    atomicAdd(&g_pool[b * HIDDEN + j], v);
    if (j == 0) atomicAdd(&g_cnt[b], 1.0f);
}

// ---------------- graph mean pool output ----------------
__global__ void graph_out_kernel(float* __restrict__ out) {
    int i = blockIdx.x * blockDim.x + threadIdx.x;
    if (i < NUM_GRAPHS * HIDDEN) out[i] = g_pool[i] / fmaxf(g_cnt[i >> 8], 1.0f);
}

// ---------------- launch ----------------
extern "C" void kernel_launch(void* const* d_in, const int* in_sizes, int n_in,
                              void* d_out, int out_size) {
    const float* x          = (const float*)d_in[0];
    const int*   edge_index = (const int*)d_in[1];
    const float* edge_attr  = (const float*)d_in[2];
    const int*   batch      = (const int*)d_in[3];
    const float* W_in       = (const float*)d_in[4];
    const float* b_in       = (const float*)d_in[5];
    const float* ln_in_g    = (const float*)d_in[6];
    const float* ln_in_b    = (const float*)d_in[7];
    const float* W_gat      = (const float*)d_in[8];
    const float* b_gat      = (const float*)d_in[9];
    const float* W_e        = (const float*)d_in[10];
    const float* a_src      = (const float*)d_in[11];
    const float* a_dst      = (const float*)d_in[12];
    const float* a_edge     = (const float*)d_in[13];
    const float* W_out      = (const float*)d_in[14];
    const float* b_out      = (const float*)d_in[15];
    const float* ln_out_g   = (const float*)d_in[16];
    const float* ln_out_b   = (const float*)d_in[17];

    float* out = (float*)d_out;

    float *hp_, *h_;
    cudaGetSymbolAddress((void**)&h_, g_h);
    cudaGetSymbolAddress((void**)&hp_, g_hp);

    long long node_off = (long long)out_size - (long long)N_NODES * HIDDEN;
    float* node_out = (node_off >= 0) ? out + node_off : hp_;

    static int smem_set = 0;
    if (!smem_set) {
        cudaFuncSetAttribute(gemm_mma_kernel, cudaFuncAttributeMaxDynamicSharedMemorySize,
                             GEMM_DSMEM);
        smem_set = 1;
    }

    init_kernel<<<(N_NODES + 255) / 256, 256>>>();
    input_proj_kernel<<<N_NODES, HIDDEN>>>(x, W_in, b_in, ln_in_g, ln_in_b);
    hist_kernel<<<(N_EDGES + 255) / 256, 256>>>(edge_index);
    scan_reduce_kernel<<<SCAN_BLOCKS, 256>>>();
    scan_final_kernel<<<SCAN_BLOCKS, 1024>>>();
    scatter_kernel<<<(N_EDGES + 255) / 256, 256>>>(edge_index, edge_attr);

    dim3 gemm_grid(2, (N_NODES + GBM - 1) / GBM);
    int score_blocks = (N_NODES * HEADS * 32 + 255) / 256;
    int gat_blocks = (N_NODES * 32 + 255) / 256;

    for (int l = 0; l < LAYERS; l++) {
        const float* Wl  = W_gat + (long long)l * HIDDEN * HIDDEN;
        const float* bl  = b_gat + l * HIDDEN;
        const float* Wel = W_e + l * 3 * HIDDEN;
        const float* asl = a_src + l * HEADS * HEAD_DIM;
        const float* adl = a_dst + l * HEADS * HEAD_DIM;
        const float* ael = a_edge + l * HEADS * HEAD_DIM;

        gemm_mma_kernel<<<gemm_grid, 256, GEMM_DSMEM>>>(h_, Wl, bl, hp_, N_NODES);
        node_score_kernel<<<score_blocks, 256>>>(asl, adl, Wel, ael);
        gat_fused_kernel<<<gat_blocks, 256>>>();
    }

    gemm_mma_kernel<<<gemm_grid, 256, GEMM_DSMEM>>>(h_, W_out, b_out, hp_, N_NODES);
    ln_out_kernel<<<N_NODES, HIDDEN>>>(ln_out_g, ln_out_b, batch, node_out);
    graph_out_kernel<<<(NUM_GRAPHS * HIDDEN + 255) / 256, 256>>>(out);
}